// round 10
// baseline (speedup 1.0000x reference)
#include <cuda_runtime.h>
#include <cuda_fp16.h>
#include <cstdint>

// Problem constants
#define T_TOK 4096
#define DIM   1024
#define HID   5632
#define HIDP  (HID / 2)
#define EACT  4
#define TB    1024
#define NTB   (T_TOK / TB)

// Scratch: combine weights, routing lists, G as fp16 pairs (11.5 MB)
__device__ float g_cw[T_TOK * EACT];
__device__ int   g_route[EACT * NTB * TB];
__device__ int   g_cnt[EACT * NTB];
__device__ __align__(16) uint32_t g_G[(size_t)TB * HIDP];

__device__ __forceinline__ uint32_t packh2(float lo, float hi) {
    __half2 h = __floats2half2_rn(lo, hi);
    return *reinterpret_cast<uint32_t*>(&h);
}

__device__ __forceinline__ void cp16(uint32_t* smem_ptr, const void* gptr) {
    uint32_t a = (uint32_t)__cvta_generic_to_shared(smem_ptr);
    asm volatile("cp.async.cg.shared.global [%0], [%1], 16;" :: "r"(a), "l"(gptr));
}
#define CP_COMMIT() asm volatile("cp.async.commit_group;")
#define CP_WAIT0()  asm volatile("cp.async.wait_group 0;")

__device__ __forceinline__ void mma16(float* c,
                                      uint32_t a0, uint32_t a1, uint32_t a2, uint32_t a3,
                                      uint32_t b0, uint32_t b1) {
    asm volatile(
        "mma.sync.aligned.m16n8k16.row.col.f32.f16.f16.f32 "
        "{%0,%1,%2,%3}, {%4,%5,%6,%7}, {%8,%9}, {%0,%1,%2,%3};\n"
        : "+f"(c[0]), "+f"(c[1]), "+f"(c[2]), "+f"(c[3])
        : "r"(a0), "r"(a1), "r"(a2), "r"(a3), "r"(b0), "r"(b1));
}

__device__ __forceinline__ float silu_f(float v) {
    return v / (1.0f + __expf(-v));
}

// ---------------------------------------------------------------------------
__global__ void zero_out_kernel(float4* out) {
    out[blockIdx.x * 256 + threadIdx.x] = make_float4(0.f, 0.f, 0.f, 0.f);
}

// ---------------------------------------------------------------------------
// Gate: one warp per token; experts 4..7 masked.
// ---------------------------------------------------------------------------
__global__ void gate_kernel(const float* __restrict__ x,
                            const float* __restrict__ gw) {
    int warp = (blockIdx.x * blockDim.x + threadIdx.x) >> 5;
    int lane = threadIdx.x & 31;
    if (warp >= T_TOK) return;

    const float* xr = x + (size_t)warp * DIM;
    float p0 = 0.f, p1 = 0.f, p2 = 0.f, p3 = 0.f;
    for (int d = lane; d < DIM; d += 32) {
        float xv = xr[d];
        p0 += xv * gw[0 * DIM + d];
        p1 += xv * gw[1 * DIM + d];
        p2 += xv * gw[2 * DIM + d];
        p3 += xv * gw[3 * DIM + d];
    }
    #pragma unroll
    for (int off = 16; off; off >>= 1) {
        p0 += __shfl_down_sync(0xffffffff, p0, off);
        p1 += __shfl_down_sync(0xffffffff, p1, off);
        p2 += __shfl_down_sync(0xffffffff, p2, off);
        p3 += __shfl_down_sync(0xffffffff, p3, off);
    }
    if (lane == 0) {
        float l[4] = {p0, p1, p2, p3};
        int i0 = 0;
        #pragma unroll
        for (int e = 1; e < 4; e++) if (l[e] > l[i0]) i0 = e;
        int i1 = -1;
        #pragma unroll
        for (int e = 0; e < 4; e++) {
            if (e == i0) continue;
            if (i1 < 0 || l[e] > l[i1]) i1 = e;
        }
        float w0 = 1.0f / (1.0f + __expf(l[i1] - l[i0]));
        float w1 = 1.0f - w0;
        float* cwr = g_cw + warp * 4;
        cwr[0] = 0.f; cwr[1] = 0.f; cwr[2] = 0.f; cwr[3] = 0.f;
        cwr[i0] = w0;
        cwr[i1] = w1;
    }
}

// ---------------------------------------------------------------------------
// Routing: per (expert, token-block) compaction, deterministic block scan.
// ---------------------------------------------------------------------------
__global__ void route_kernel() {
    const int e   = blockIdx.x >> 2;
    const int tb  = blockIdx.x & 3;
    const int tid = threadIdx.x;
    const int t0  = tb * TB;

    int flags[4];
    int myc = 0;
    #pragma unroll
    for (int j = 0; j < 4; j++) {
        int t = t0 + tid * 4 + j;
        int f = (g_cw[t * 4 + e] > 0.f) ? 1 : 0;
        flags[j] = f;
        myc += f;
    }

    __shared__ int sc[256];
    sc[tid] = myc;
    __syncthreads();
    #pragma unroll
    for (int off = 1; off < 256; off <<= 1) {
        int v = (tid >= off) ? sc[tid - off] : 0;
        __syncthreads();
        sc[tid] += v;
        __syncthreads();
    }
    int pos = sc[tid] - myc;

    int* lst = g_route + (e * NTB + tb) * TB;
    #pragma unroll
    for (int j = 0; j < 4; j++) {
        if (flags[j]) lst[pos++] = t0 + tid * 4 + j;
    }
    if (tid == 255) g_cnt[e * NTB + tb] = sc[255];
}

// ---------------------------------------------------------------------------
// GEMM13 (routed, fp16 mma): BM=128, BN=64, BK=32.
// A (gathered X) f32 in smem via cp.async, stride 40 words (conflict-free
// LDS.64 per half-warp phase), packed to fp16x2 at fragment load.
// B1/B3 staged LDG->pack->STS as fp16 pairs [16][72] (conflict-free).
// Stage = 5120 + 1152 + 1152 = 7424 words; 2 stages = 59392 B dynamic smem.
// ---------------------------------------------------------------------------
#define G13_STAGE 7424
#define G13_ITERS (DIM / 32)

__device__ __forceinline__ void g13_cpA(
    uint32_t* sm, const int* toks, int s, int k0, const float* X, int tid)
{
    uint32_t* A = sm + s * G13_STAGE;
    int row  = tid >> 1;
    int half = tid & 1;
    const float* src = X + (size_t)toks[row] * DIM + k0 + half * 16;
    #pragma unroll
    for (int j = 0; j < 4; j++)
        cp16(A + row * 40 + half * 16 + j * 4, src + j * 4);
    CP_COMMIT();
}

__device__ __forceinline__ void g13_ldgB(
    const float* W1, const float* W3, int k0, int tid, int bn,
    float4* b1R, float4* b3R)
{
    int kp = tid >> 4;
    int n4 = (tid & 15) * 4;
    size_t o0 = (size_t)(k0 + 2 * kp) * HID + bn + n4;
    b1R[0] = *(const float4*)(W1 + o0);
    b1R[1] = *(const float4*)(W1 + o0 + HID);
    b3R[0] = *(const float4*)(W3 + o0);
    b3R[1] = *(const float4*)(W3 + o0 + HID);
}

__device__ __forceinline__ void g13_stsB(
    uint32_t* sm, int s, int tid, const float4* b1R, const float4* b3R)
{
    uint32_t* B1 = sm + s * G13_STAGE + 5120;
    uint32_t* B3 = B1 + 1152;
    int kp = tid >> 4;
    int n4 = (tid & 15) * 4;
    uint4 v1 = make_uint4(packh2(b1R[0].x, b1R[1].x), packh2(b1R[0].y, b1R[1].y),
                          packh2(b1R[0].z, b1R[1].z), packh2(b1R[0].w, b1R[1].w));
    uint4 v3 = make_uint4(packh2(b3R[0].x, b3R[1].x), packh2(b3R[0].y, b3R[1].y),
                          packh2(b3R[0].z, b3R[1].z), packh2(b3R[0].w, b3R[1].w));
    *(uint4*)(B1 + kp * 72 + n4) = v1;
    *(uint4*)(B3 + kp * 72 + n4) = v3;
}

__global__ void __launch_bounds__(256, 2) gemm13_kernel(
    const float* __restrict__ X,
    const float* __restrict__ W1,
    const float* __restrict__ W3,
    int eidx, int tb)
{
    const int cnt = g_cnt[eidx * NTB + tb];
    const int bm  = blockIdx.y * 128;
    if (bm >= cnt) return;

    extern __shared__ __align__(16) uint32_t sm[];
    __shared__ int toks[128];

    const int tid  = threadIdx.x;
    const int bn   = blockIdx.x * 64;
    const int warp = tid >> 5;
    const int lane = tid & 31;
    const int wm   = (warp & 3) * 32;
    const int wn   = (warp >> 2) * 32;
    const int g    = lane >> 2;
    const int tig  = lane & 3;

    if (tid < 128) {
        int slot = bm + tid;
        if (slot >= cnt) slot = cnt - 1;
        toks[tid] = g_route[(eidx * NTB + tb) * TB + slot];
    }
    __syncthreads();

    float accA[2][4][4];
    float accB[2][4][4];
    #pragma unroll
    for (int mt = 0; mt < 2; mt++)
        #pragma unroll
        for (int nt = 0; nt < 4; nt++)
            #pragma unroll
            for (int i = 0; i < 4; i++) { accA[mt][nt][i] = 0.f; accB[mt][nt][i] = 0.f; }

    float4 b1R[2], b3R[2];
    g13_cpA(sm, toks, 0, 0, X, tid);
    g13_ldgB(W1, W3, 0, tid, bn, b1R, b3R);
    g13_stsB(sm, 0, tid, b1R, b3R);
    CP_WAIT0();
    __syncthreads();

    for (int it = 0; it < G13_ITERS; it++) {
        int s = it & 1;
        bool pf = (it + 1 < G13_ITERS);
        if (pf) {
            g13_cpA(sm, toks, s ^ 1, (it + 1) * 32, X, tid);
            g13_ldgB(W1, W3, (it + 1) * 32, tid, bn, b1R, b3R);
        }

        const uint32_t* A  = sm + s * G13_STAGE;
        const uint32_t* B1 = A + 5120;
        const uint32_t* B3 = B1 + 1152;

        #pragma unroll
        for (int ks = 0; ks < 2; ks++) {
            uint32_t a[2][4];
            const int c0 = ks * 8 + tig;
            #pragma unroll
            for (int mt = 0; mt < 2; mt++) {
                int r = wm + mt * 16 + g;
                float2 v;
                v = *(const float2*)&A[(size_t)r * 40 + 2 * c0];
                a[mt][0] = packh2(v.x, v.y);
                v = *(const float2*)&A[(size_t)(r + 8) * 40 + 2 * c0];
                a[mt][1] = packh2(v.x, v.y);
                v = *(const float2*)&A[(size_t)r * 40 + 2 * (c0 + 4)];
                a[mt][2] = packh2(v.x, v.y);
                v = *(const float2*)&A[(size_t)(r + 8) * 40 + 2 * (c0 + 4)];
                a[mt][3] = packh2(v.x, v.y);
            }
            #pragma unroll
            for (int nt = 0; nt < 4; nt++) {
                int n = wn + nt * 8 + g;
                uint32_t b1a = B1[c0 * 72 + n];
                uint32_t b1b = B1[(c0 + 4) * 72 + n];
                uint32_t b3a = B3[c0 * 72 + n];
                uint32_t b3b = B3[(c0 + 4) * 72 + n];
                #pragma unroll
                for (int mt = 0; mt < 2; mt++) {
                    mma16(accA[mt][nt], a[mt][0], a[mt][1], a[mt][2], a[mt][3], b1a, b1b);
                    mma16(accB[mt][nt], a[mt][0], a[mt][1], a[mt][2], a[mt][3], b3a, b3b);
                }
            }
        }

        __syncthreads();
        if (pf) {
            g13_stsB(sm, s ^ 1, tid, b1R, b3R);
            CP_WAIT0();
        }
        __syncthreads();
    }

    // epilogue: G pairs = fp16(cw * silu(A) * B)
    #pragma unroll
    for (int mt = 0; mt < 2; mt++) {
        int lr0 = wm + mt * 16 + g;
        int lr1 = lr0 + 8;
        float cw0 = g_cw[toks[lr0] * 4 + eidx];
        float cw1 = g_cw[toks[lr1] * 4 + eidx];
        size_t r0 = (size_t)(bm + lr0) * HIDP;
        size_t r1 = (size_t)(bm + lr1) * HIDP;
        #pragma unroll
        for (int nt = 0; nt < 4; nt++) {
            int cp = ((bn + wn + nt * 8) >> 1) + tig;
            float v00 = silu_f(accA[mt][nt][0]) * accB[mt][nt][0] * cw0;
            float v01 = silu_f(accA[mt][nt][1]) * accB[mt][nt][1] * cw0;
            float v10 = silu_f(accA[mt][nt][2]) * accB[mt][nt][2] * cw1;
            float v11 = silu_f(accA[mt][nt][3]) * accB[mt][nt][3] * cw1;
            g_G[r0 + cp] = packh2(v00, v01);
            g_G[r1 + cp] = packh2(v10, v11);
        }
    }
}

// ---------------------------------------------------------------------------
// GEMM2 (routed, fp16 mma): BM=64, BN=64, BK=32; 256 thr, 8 warps 32x16.
// A = g_G fp16 pairs via cp.async (stride 20 words, conflict-free).
// B = W2 staged LDG->pack->STS [16][72]. Static smem 19456 B.
// ---------------------------------------------------------------------------
#define G2_STAGE 2432
#define G2_ITERS (HID / 32)

__device__ __forceinline__ void g2_cpA(
    uint32_t* smb, int s, int kp0, int tid, int bm)
{
    uint32_t* A = smb + s * G2_STAGE;
    int r = tid >> 2;
    int q = tid & 3;
    cp16(A + r * 20 + q * 4, g_G + (size_t)(bm + r) * HIDP + kp0 + q * 4);
    CP_COMMIT();
}

__device__ __forceinline__ void g2_ldgB(
    const float* W2, int k0, int tid, int bn, float4* bR)
{
    int kp = tid >> 4;
    int n4 = (tid & 15) * 4;
    size_t o0 = (size_t)(k0 + 2 * kp) * DIM + bn + n4;
    bR[0] = *(const float4*)(W2 + o0);
    bR[1] = *(const float4*)(W2 + o0 + DIM);
}

__device__ __forceinline__ void g2_stsB(
    uint32_t* smb, int s, int tid, const float4* bR)
{
    uint32_t* B = smb + s * G2_STAGE + 1280;
    int kp = tid >> 4;
    int n4 = (tid & 15) * 4;
    uint4 v = make_uint4(packh2(bR[0].x, bR[1].x), packh2(bR[0].y, bR[1].y),
                         packh2(bR[0].z, bR[1].z), packh2(bR[0].w, bR[1].w));
    *(uint4*)(B + kp * 72 + n4) = v;
}

__global__ void __launch_bounds__(256) gemm2_kernel(
    const float* __restrict__ W2,
    float* __restrict__ out,
    int eidx, int tb)
{
    const int cnt = g_cnt[eidx * NTB + tb];
    const int bm  = blockIdx.y * 64;
    if (bm >= cnt) return;

    __shared__ __align__(16) uint32_t sm2[2 * G2_STAGE];

    const int tid  = threadIdx.x;
    const int bn   = blockIdx.x * 64;
    const int warp = tid >> 5;
    const int lane = tid & 31;
    const int wm   = (warp & 1) * 32;
    const int wn   = (warp >> 1) * 16;
    const int g    = lane >> 2;
    const int tig  = lane & 3;

    float acc[2][2][4];
    #pragma unroll
    for (int mt = 0; mt < 2; mt++)
        #pragma unroll
        for (int nt = 0; nt < 2; nt++)
            #pragma unroll
            for (int i = 0; i < 4; i++) acc[mt][nt][i] = 0.f;

    float4 bR[2];
    g2_cpA(sm2, 0, 0, tid, bm);
    g2_ldgB(W2, 0, tid, bn, bR);
    g2_stsB(sm2, 0, tid, bR);
    CP_WAIT0();
    __syncthreads();

    for (int it = 0; it < G2_ITERS; it++) {
        int s = it & 1;
        bool pf = (it + 1 < G2_ITERS);
        if (pf) {
            g2_cpA(sm2, s ^ 1, (it + 1) * 16, tid, bm);
            g2_ldgB(W2, (it + 1) * 32, tid, bn, bR);
        }

        const uint32_t* A = sm2 + s * G2_STAGE;
        const uint32_t* B = A + 1280;

        #pragma unroll
        for (int ks = 0; ks < 2; ks++) {
            const int c0 = ks * 8 + tig;
            uint32_t a[2][4];
            #pragma unroll
            for (int mt = 0; mt < 2; mt++) {
                int r = wm + mt * 16 + g;
                a[mt][0] = A[r * 20 + c0];
                a[mt][1] = A[(r + 8) * 20 + c0];
                a[mt][2] = A[r * 20 + c0 + 4];
                a[mt][3] = A[(r + 8) * 20 + c0 + 4];
            }
            #pragma unroll
            for (int nt = 0; nt < 2; nt++) {
                int n = wn + nt * 8 + g;
                uint32_t b0 = B[c0 * 72 + n];
                uint32_t b1 = B[(c0 + 4) * 72 + n];
                #pragma unroll
                for (int mt = 0; mt < 2; mt++)
                    mma16(acc[mt][nt], a[mt][0], a[mt][1], a[mt][2], a[mt][3], b0, b1);
            }
        }

        __syncthreads();
        if (pf) {
            g2_stsB(sm2, s ^ 1, tid, bR);
            CP_WAIT0();
        }
        __syncthreads();
    }

    // epilogue: scatter-accumulate into out (guard rows >= cnt)
    const int* lst = g_route + (eidx * NTB + tb) * TB;
    #pragma unroll
    for (int mt = 0; mt < 2; mt++) {
        int lr0 = wm + mt * 16 + g;
        int lr1 = lr0 + 8;
        int s0 = bm + lr0;
        int s1 = bm + lr1;
        bool v0ok = s0 < cnt;
        bool v1ok = s1 < cnt;
        int t0 = v0ok ? lst[s0] : 0;
        int t1 = v1ok ? lst[s1] : 0;
        #pragma unroll
        for (int nt = 0; nt < 2; nt++) {
            int c = bn + wn + nt * 8 + 2 * tig;
            if (v0ok) {
                float2* p = (float2*)&out[(size_t)t0 * DIM + c];
                float2 o = *p;
                o.x += acc[mt][nt][0];
                o.y += acc[mt][nt][1];
                *p = o;
            }
            if (v1ok) {
                float2* p = (float2*)&out[(size_t)t1 * DIM + c];
                float2 o = *p;
                o.x += acc[mt][nt][2];
                o.y += acc[mt][nt][3];
                *p = o;
            }
        }
    }
}

// ---------------------------------------------------------------------------
extern "C" void kernel_launch(void* const* d_in, const int* in_sizes, int n_in,
                              void* d_out, int out_size) {
    const float* x   = (const float*)d_in[0];
    const float* gw  = (const float*)d_in[1];
    const float* w1  = (const float*)d_in[2];
    const float* w2  = (const float*)d_in[3];
    const float* w3  = (const float*)d_in[4];
    float* out = (float*)d_out;

    cudaFuncSetAttribute(gemm13_kernel,
                         cudaFuncAttributeMaxDynamicSharedMemorySize, 2 * G13_STAGE * 4);

    zero_out_kernel<<<(T_TOK * DIM) / (256 * 4), 256>>>((float4*)out);
    gate_kernel<<<T_TOK / 4, 128>>>(x, gw);
    route_kernel<<<EACT * NTB, 256>>>();

    for (int e = 0; e < EACT; e++) {
        const float* w1e = w1 + (size_t)e * DIM * HID;
        const float* w3e = w3 + (size_t)e * DIM * HID;
        const float* w2e = w2 + (size_t)e * HID * DIM;
        for (int tb = 0; tb < NTB; tb++) {
            gemm13_kernel<<<dim3(HID / 64, TB / 128), 256, 2 * G13_STAGE * 4>>>(x, w1e, w3e, e, tb);
            gemm2_kernel<<<dim3(DIM / 64, TB / 64), 256>>>(w2e, out, e, tb);
        }
    }
}

// round 11
// speedup vs baseline: 2.5440x; 2.5440x over previous
#include <cuda_runtime.h>
#include <cstdint>

// Problem constants
#define T_TOK 4096
#define DIM   1024
#define HID   5632
#define EACT  4
#define TB    1024
#define NTB   (T_TOK / TB)

// Scratch: combine weights, routing, G (tf32 bits) for a FULL expert (92 MB)
__device__ float g_cw[T_TOK * EACT];
__device__ int   g_route[EACT * NTB * TB];
__device__ int   g_cnt[EACT * NTB];
__device__ __align__(16) uint32_t g_G[(size_t)T_TOK * HID];

__device__ __forceinline__ uint32_t f2tf32(float f) {
    uint32_t r;
    asm("cvt.rna.tf32.f32 %0, %1;" : "=r"(r) : "f"(f));
    return r;
}
__device__ __forceinline__ uint32_t b2tf32(uint32_t b) {
    return f2tf32(__uint_as_float(b));
}

__device__ __forceinline__ void cp16(uint32_t* smem_ptr, const void* gptr) {
    uint32_t a = (uint32_t)__cvta_generic_to_shared(smem_ptr);
    asm volatile("cp.async.cg.shared.global [%0], [%1], 16;" :: "r"(a), "l"(gptr));
}
#define CP_COMMIT() asm volatile("cp.async.commit_group;")
#define CP_WAIT0()  asm volatile("cp.async.wait_group 0;")

__device__ __forceinline__ void mma8(float* c,
                                     uint32_t a0, uint32_t a1, uint32_t a2, uint32_t a3,
                                     uint32_t b0, uint32_t b1) {
    asm volatile(
        "mma.sync.aligned.m16n8k8.row.col.f32.tf32.tf32.f32 "
        "{%0,%1,%2,%3}, {%4,%5,%6,%7}, {%8,%9}, {%0,%1,%2,%3};\n"
        : "+f"(c[0]), "+f"(c[1]), "+f"(c[2]), "+f"(c[3])
        : "r"(a0), "r"(a1), "r"(a2), "r"(a3), "r"(b0), "r"(b1));
}

__device__ __forceinline__ float silu_f(float v) {
    return v / (1.0f + __expf(-v));
}

// ---------------------------------------------------------------------------
__global__ void zero_out_kernel(float4* out) {
    out[blockIdx.x * 256 + threadIdx.x] = make_float4(0.f, 0.f, 0.f, 0.f);
}

// ---------------------------------------------------------------------------
// Gate: one warp per token; experts 4..7 masked.
// ---------------------------------------------------------------------------
__global__ void gate_kernel(const float* __restrict__ x,
                            const float* __restrict__ gw) {
    int warp = (blockIdx.x * blockDim.x + threadIdx.x) >> 5;
    int lane = threadIdx.x & 31;
    if (warp >= T_TOK) return;

    const float* xr = x + (size_t)warp * DIM;
    float p0 = 0.f, p1 = 0.f, p2 = 0.f, p3 = 0.f;
    for (int d = lane; d < DIM; d += 32) {
        float xv = xr[d];
        p0 += xv * gw[0 * DIM + d];
        p1 += xv * gw[1 * DIM + d];
        p2 += xv * gw[2 * DIM + d];
        p3 += xv * gw[3 * DIM + d];
    }
    #pragma unroll
    for (int off = 16; off; off >>= 1) {
        p0 += __shfl_down_sync(0xffffffff, p0, off);
        p1 += __shfl_down_sync(0xffffffff, p1, off);
        p2 += __shfl_down_sync(0xffffffff, p2, off);
        p3 += __shfl_down_sync(0xffffffff, p3, off);
    }
    if (lane == 0) {
        float l[4] = {p0, p1, p2, p3};
        int i0 = 0;
        #pragma unroll
        for (int e = 1; e < 4; e++) if (l[e] > l[i0]) i0 = e;
        int i1 = -1;
        #pragma unroll
        for (int e = 0; e < 4; e++) {
            if (e == i0) continue;
            if (i1 < 0 || l[e] > l[i1]) i1 = e;
        }
        float w0 = 1.0f / (1.0f + __expf(l[i1] - l[i0]));
        float w1 = 1.0f - w0;
        float* cwr = g_cw + warp * 4;
        cwr[0] = 0.f; cwr[1] = 0.f; cwr[2] = 0.f; cwr[3] = 0.f;
        cwr[i0] = w0;
        cwr[i1] = w1;
    }
}

// ---------------------------------------------------------------------------
// Routing: per (expert, token-block) compaction, deterministic block scan.
// ---------------------------------------------------------------------------
__global__ void route_kernel() {
    const int e   = blockIdx.x >> 2;
    const int tb  = blockIdx.x & 3;
    const int tid = threadIdx.x;
    const int t0  = tb * TB;

    int flags[4];
    int myc = 0;
    #pragma unroll
    for (int j = 0; j < 4; j++) {
        int t = t0 + tid * 4 + j;
        int f = (g_cw[t * 4 + e] > 0.f) ? 1 : 0;
        flags[j] = f;
        myc += f;
    }

    __shared__ int sc[256];
    sc[tid] = myc;
    __syncthreads();
    #pragma unroll
    for (int off = 1; off < 256; off <<= 1) {
        int v = (tid >= off) ? sc[tid - off] : 0;
        __syncthreads();
        sc[tid] += v;
        __syncthreads();
    }
    int pos = sc[tid] - myc;

    int* lst = g_route + (e * NTB + tb) * TB;
    #pragma unroll
    for (int j = 0; j < 4; j++) {
        if (flags[j]) lst[pos++] = t0 + tid * 4 + j;
    }
    if (tid == 255) g_cnt[e * NTB + tb] = sc[255];
}

// ---------------------------------------------------------------------------
// GEMM13 (routed, merged over tb via blockIdx.z):
// G[tb*TB+s,h] = tf32( cw[t,e] * silu(X[t]@W1)[h] * (X[t]@W3)[h] )
// BM=128, BN=64, BK=32; 2-stage cp.async; XOR-swizzled smem. 64KB dynamic.
// ---------------------------------------------------------------------------
#define G13_STAGE_WORDS 8192
#define G13_ITERS (DIM / 32)

__device__ __forceinline__ void g13_load_stage(
    uint32_t* sm, const int* toks, int s, int k0,
    const float* X, const float* W1, const float* W3,
    int tid, int bn)
{
    uint32_t* A  = sm + s * G13_STAGE_WORDS;
    uint32_t* B1 = A + 4096;
    uint32_t* B3 = A + 6144;
    #pragma unroll
    for (int i = 0; i < 4; i++) {
        int id  = tid + i * 256;
        int row = id >> 3;
        int c4  = (id & 7) * 4;
        cp16(A + row * 32 + (c4 ^ ((row & 7) * 4)),
             X + (size_t)toks[row] * DIM + k0 + c4);
    }
    #pragma unroll
    for (int i = 0; i < 2; i++) {
        int id  = tid + i * 256;
        int row = id >> 4;
        int c4  = (id & 15) * 4;
        int pc  = c4 ^ ((row & 3) * 8);
        size_t goff = (size_t)(k0 + row) * HID + bn + c4;
        cp16(B1 + row * 64 + pc, W1 + goff);
        cp16(B3 + row * 64 + pc, W3 + goff);
    }
    CP_COMMIT();
}

__global__ void __launch_bounds__(256, 2) gemm13_kernel(
    const float* __restrict__ X,
    const float* __restrict__ W1,
    const float* __restrict__ W3,
    int eidx)
{
    const int tb  = blockIdx.z;
    const int cnt = g_cnt[eidx * NTB + tb];
    const int bm  = blockIdx.y * 128;
    if (bm >= cnt) return;

    extern __shared__ __align__(16) uint32_t sm[];
    __shared__ int toks[128];

    const int tid  = threadIdx.x;
    const int bn   = blockIdx.x * 64;
    const int warp = tid >> 5;
    const int lane = tid & 31;
    const int wm   = (warp & 3) * 32;
    const int wn   = (warp >> 2) * 32;
    const int g    = lane >> 2;
    const int tig  = lane & 3;

    if (tid < 128) {
        int slot = bm + tid;
        if (slot >= cnt) slot = cnt - 1;
        toks[tid] = g_route[(eidx * NTB + tb) * TB + slot];
    }
    __syncthreads();

    float accA[2][4][4];
    float accB[2][4][4];
    #pragma unroll
    for (int mt = 0; mt < 2; mt++)
        #pragma unroll
        for (int nt = 0; nt < 4; nt++)
            #pragma unroll
            for (int i = 0; i < 4; i++) { accA[mt][nt][i] = 0.f; accB[mt][nt][i] = 0.f; }

    g13_load_stage(sm, toks, 0, 0, X, W1, W3, tid, bn);

    for (int it = 0; it < G13_ITERS; it++) {
        CP_WAIT0();
        __syncthreads();
        int s = it & 1;
        if (it + 1 < G13_ITERS)
            g13_load_stage(sm, toks, s ^ 1, (it + 1) * 32, X, W1, W3, tid, bn);

        const uint32_t* A  = sm + s * G13_STAGE_WORDS;
        const uint32_t* B1 = A + 4096;
        const uint32_t* B3 = A + 6144;

        #pragma unroll
        for (int kk = 0; kk < 32; kk += 8) {
            uint32_t a[2][4];
            const int xo = 4 * g;
            #pragma unroll
            for (int mt = 0; mt < 2; mt++) {
                int r = wm + mt * 16 + g;
                a[mt][0] = b2tf32(A[(size_t)r * 32 + ((kk + tig) ^ xo)]);
                a[mt][1] = b2tf32(A[(size_t)(r + 8) * 32 + ((kk + tig) ^ xo)]);
                a[mt][2] = b2tf32(A[(size_t)r * 32 + ((kk + tig + 4) ^ xo)]);
                a[mt][3] = b2tf32(A[(size_t)(r + 8) * 32 + ((kk + tig + 4) ^ xo)]);
            }
            const int krow = kk + tig;
            const int ko   = (krow & 3) * 8;
            #pragma unroll
            for (int nt = 0; nt < 4; nt++) {
                int n  = wn + nt * 8 + g;
                int pc = n ^ ko;
                uint32_t b1a = b2tf32(B1[krow * 64 + pc]);
                uint32_t b1b = b2tf32(B1[(krow + 4) * 64 + pc]);
                uint32_t b3a = b2tf32(B3[krow * 64 + pc]);
                uint32_t b3b = b2tf32(B3[(krow + 4) * 64 + pc]);
                #pragma unroll
                for (int mt = 0; mt < 2; mt++) {
                    mma8(accA[mt][nt], a[mt][0], a[mt][1], a[mt][2], a[mt][3], b1a, b1b);
                    mma8(accB[mt][nt], a[mt][0], a[mt][1], a[mt][2], a[mt][3], b3a, b3b);
                }
            }
        }
    }

    // epilogue: G[tb*TB + slot] = tf32(cw * silu(A) * B)
    #pragma unroll
    for (int mt = 0; mt < 2; mt++) {
        int lr0 = wm + mt * 16 + g;
        int lr1 = lr0 + 8;
        float cw0 = g_cw[toks[lr0] * 4 + eidx];
        float cw1 = g_cw[toks[lr1] * 4 + eidx];
        size_t r0 = (size_t)(tb * TB + bm + lr0) * HID;
        size_t r1 = (size_t)(tb * TB + bm + lr1) * HID;
        #pragma unroll
        for (int nt = 0; nt < 4; nt++) {
            int c = bn + wn + nt * 8 + 2 * tig;
            float v00 = silu_f(accA[mt][nt][0]) * accB[mt][nt][0] * cw0;
            float v01 = silu_f(accA[mt][nt][1]) * accB[mt][nt][1] * cw0;
            float v10 = silu_f(accA[mt][nt][2]) * accB[mt][nt][2] * cw1;
            float v11 = silu_f(accA[mt][nt][3]) * accB[mt][nt][3] * cw1;
            *(uint2*)&g_G[r0 + c] = make_uint2(f2tf32(v00), f2tf32(v01));
            *(uint2*)&g_G[r1 + c] = make_uint2(f2tf32(v10), f2tf32(v11));
        }
    }
}

// ---------------------------------------------------------------------------
// GEMM2 (routed, merged over tb via blockIdx.z):
// out[route[s],d] += (G[tb*TB+s,:] @ W2)[d] for s < cnt.
// BM=64, BN=64, BK=32; 256 thr (8 warps, 32x16); 2-stage cp.async. 32KB smem.
// ---------------------------------------------------------------------------
#define G2_STAGE_WORDS 4096
#define G2_ITERS (HID / 32)

__device__ __forceinline__ void g2_load_stage(
    uint32_t* smb, int s, int k0,
    const float* W2, int tid, int gm0, int bn)
{
    uint32_t* A = smb + s * G2_STAGE_WORDS;
    uint32_t* B = A + 2048;
    #pragma unroll
    for (int i = 0; i < 2; i++) {
        int id  = tid + i * 256;
        int row = id >> 3;
        int c4  = (id & 7) * 4;
        cp16(A + row * 32 + (c4 ^ ((row & 7) * 4)),
             g_G + (size_t)(gm0 + row) * HID + k0 + c4);
    }
    #pragma unroll
    for (int i = 0; i < 2; i++) {
        int id  = tid + i * 256;
        int row = id >> 4;
        int c4  = (id & 15) * 4;
        cp16(B + row * 64 + (c4 ^ ((row & 3) * 8)),
             W2 + (size_t)(k0 + row) * DIM + bn + c4);
    }
    CP_COMMIT();
}

__global__ void __launch_bounds__(256) gemm2_kernel(
    const float* __restrict__ W2,
    float* __restrict__ out,
    int eidx)
{
    const int tb  = blockIdx.z;
    const int cnt = g_cnt[eidx * NTB + tb];
    const int bm  = blockIdx.y * 64;
    if (bm >= cnt) return;
    const int gm0 = tb * TB + bm;

    __shared__ __align__(16) uint32_t sm2[2 * G2_STAGE_WORDS];

    const int tid  = threadIdx.x;
    const int bn   = blockIdx.x * 64;
    const int warp = tid >> 5;
    const int lane = tid & 31;
    const int wm   = (warp & 1) * 32;
    const int wn   = (warp >> 1) * 16;
    const int g    = lane >> 2;
    const int tig  = lane & 3;

    float acc[2][2][4];
    #pragma unroll
    for (int mt = 0; mt < 2; mt++)
        #pragma unroll
        for (int nt = 0; nt < 2; nt++)
            #pragma unroll
            for (int i = 0; i < 4; i++) acc[mt][nt][i] = 0.f;

    g2_load_stage(sm2, 0, 0, W2, tid, gm0, bn);

    for (int it = 0; it < G2_ITERS; it++) {
        CP_WAIT0();
        __syncthreads();
        int s = it & 1;
        if (it + 1 < G2_ITERS)
            g2_load_stage(sm2, s ^ 1, (it + 1) * 32, W2, tid, gm0, bn);

        const uint32_t* A = sm2 + s * G2_STAGE_WORDS;
        const uint32_t* B = A + 2048;

        #pragma unroll
        for (int kk = 0; kk < 32; kk += 8) {
            uint32_t a[2][4];
            const int xo = 4 * g;
            #pragma unroll
            for (int mt = 0; mt < 2; mt++) {
                int r = wm + mt * 16 + g;
                a[mt][0] = A[(size_t)r * 32 + ((kk + tig) ^ xo)];
                a[mt][1] = A[(size_t)(r + 8) * 32 + ((kk + tig) ^ xo)];
                a[mt][2] = A[(size_t)r * 32 + ((kk + tig + 4) ^ xo)];
                a[mt][3] = A[(size_t)(r + 8) * 32 + ((kk + tig + 4) ^ xo)];
            }
            const int krow = kk + tig;
            const int ko   = (krow & 3) * 8;
            #pragma unroll
            for (int nt = 0; nt < 2; nt++) {
                int n  = wn + nt * 8 + g;
                int pc = n ^ ko;
                uint32_t b0 = b2tf32(B[krow * 64 + pc]);
                uint32_t b1 = b2tf32(B[(krow + 4) * 64 + pc]);
                #pragma unroll
                for (int mt = 0; mt < 2; mt++)
                    mma8(acc[mt][nt], a[mt][0], a[mt][1], a[mt][2], a[mt][3], b0, b1);
            }
        }
    }

    // epilogue: scatter-accumulate into out (guard rows >= cnt)
    const int* lst = g_route + (eidx * NTB + tb) * TB;
    #pragma unroll
    for (int mt = 0; mt < 2; mt++) {
        int lr0 = wm + mt * 16 + g;
        int lr1 = lr0 + 8;
        int s0 = bm + lr0;
        int s1 = bm + lr1;
        bool v0ok = s0 < cnt;
        bool v1ok = s1 < cnt;
        int t0 = v0ok ? lst[s0] : 0;
        int t1 = v1ok ? lst[s1] : 0;
        #pragma unroll
        for (int nt = 0; nt < 2; nt++) {
            int c = bn + wn + nt * 8 + 2 * tig;
            if (v0ok) {
                float2* p = (float2*)&out[(size_t)t0 * DIM + c];
                float2 o = *p;
                o.x += acc[mt][nt][0];
                o.y += acc[mt][nt][1];
                *p = o;
            }
            if (v1ok) {
                float2* p = (float2*)&out[(size_t)t1 * DIM + c];
                float2 o = *p;
                o.x += acc[mt][nt][2];
                o.y += acc[mt][nt][3];
                *p = o;
            }
        }
    }
}

// ---------------------------------------------------------------------------
extern "C" void kernel_launch(void* const* d_in, const int* in_sizes, int n_in,
                              void* d_out, int out_size) {
    const float* x   = (const float*)d_in[0];
    const float* gw  = (const float*)d_in[1];
    const float* w1  = (const float*)d_in[2];
    const float* w2  = (const float*)d_in[3];
    const float* w3  = (const float*)d_in[4];
    float* out = (float*)d_out;

    cudaFuncSetAttribute(gemm13_kernel,
                         cudaFuncAttributeMaxDynamicSharedMemorySize, 65536);

    zero_out_kernel<<<(T_TOK * DIM) / (256 * 4), 256>>>((float4*)out);
    gate_kernel<<<T_TOK / 4, 128>>>(x, gw);
    route_kernel<<<EACT * NTB, 256>>>();

    for (int e = 0; e < EACT; e++) {
        const float* w1e = w1 + (size_t)e * DIM * HID;
        const float* w3e = w3 + (size_t)e * DIM * HID;
        const float* w2e = w2 + (size_t)e * HID * DIM;
        gemm13_kernel<<<dim3(HID / 64, TB / 128, NTB), 256, 65536>>>(x, w1e, w3e, e);
        gemm2_kernel<<<dim3(DIM / 64, TB / 64, NTB), 256>>>(w2e, out, e);
    }
}

// round 12
// speedup vs baseline: 2.7595x; 1.0847x over previous
#include <cuda_runtime.h>
#include <cstdint>

// Problem constants
#define T_TOK 4096
#define DIM   1024
#define HID   5632
#define EACT  4
#define TB    1024
#define NTB   (T_TOK / TB)

// Scratch: combine weights, routing, G (tf32 bits) for a FULL expert (92 MB)
__device__ float g_cw[T_TOK * EACT];
__device__ int   g_route[EACT * NTB * TB];
__device__ int   g_cnt[EACT * NTB];
__device__ __align__(16) uint32_t g_G[(size_t)T_TOK * HID];

__device__ __forceinline__ uint32_t f2tf32(float f) {
    uint32_t r;
    asm("cvt.rna.tf32.f32 %0, %1;" : "=r"(r) : "f"(f));
    return r;
}
__device__ __forceinline__ uint32_t b2tf32(uint32_t b) {
    return f2tf32(__uint_as_float(b));
}

__device__ __forceinline__ void cp16(uint32_t* smem_ptr, const void* gptr) {
    uint32_t a = (uint32_t)__cvta_generic_to_shared(smem_ptr);
    asm volatile("cp.async.cg.shared.global [%0], [%1], 16;" :: "r"(a), "l"(gptr));
}
#define CP_COMMIT() asm volatile("cp.async.commit_group;")
#define CP_WAIT0()  asm volatile("cp.async.wait_group 0;")

__device__ __forceinline__ void mma8(float* c,
                                     uint32_t a0, uint32_t a1, uint32_t a2, uint32_t a3,
                                     uint32_t b0, uint32_t b1) {
    asm volatile(
        "mma.sync.aligned.m16n8k8.row.col.f32.tf32.tf32.f32 "
        "{%0,%1,%2,%3}, {%4,%5,%6,%7}, {%8,%9}, {%0,%1,%2,%3};\n"
        : "+f"(c[0]), "+f"(c[1]), "+f"(c[2]), "+f"(c[3])
        : "r"(a0), "r"(a1), "r"(a2), "r"(a3), "r"(b0), "r"(b1));
}

__device__ __forceinline__ float silu_f(float v) {
    return v / (1.0f + __expf(-v));
}

// ---------------------------------------------------------------------------
__global__ void zero_out_kernel(float4* out) {
    out[blockIdx.x * 256 + threadIdx.x] = make_float4(0.f, 0.f, 0.f, 0.f);
}

// ---------------------------------------------------------------------------
// Gate: one warp per token; experts 4..7 masked.
// ---------------------------------------------------------------------------
__global__ void gate_kernel(const float* __restrict__ x,
                            const float* __restrict__ gw) {
    int warp = (blockIdx.x * blockDim.x + threadIdx.x) >> 5;
    int lane = threadIdx.x & 31;
    if (warp >= T_TOK) return;

    const float* xr = x + (size_t)warp * DIM;
    float p0 = 0.f, p1 = 0.f, p2 = 0.f, p3 = 0.f;
    for (int d = lane; d < DIM; d += 32) {
        float xv = xr[d];
        p0 += xv * gw[0 * DIM + d];
        p1 += xv * gw[1 * DIM + d];
        p2 += xv * gw[2 * DIM + d];
        p3 += xv * gw[3 * DIM + d];
    }
    #pragma unroll
    for (int off = 16; off; off >>= 1) {
        p0 += __shfl_down_sync(0xffffffff, p0, off);
        p1 += __shfl_down_sync(0xffffffff, p1, off);
        p2 += __shfl_down_sync(0xffffffff, p2, off);
        p3 += __shfl_down_sync(0xffffffff, p3, off);
    }
    if (lane == 0) {
        float l[4] = {p0, p1, p2, p3};
        int i0 = 0;
        #pragma unroll
        for (int e = 1; e < 4; e++) if (l[e] > l[i0]) i0 = e;
        int i1 = -1;
        #pragma unroll
        for (int e = 0; e < 4; e++) {
            if (e == i0) continue;
            if (i1 < 0 || l[e] > l[i1]) i1 = e;
        }
        float w0 = 1.0f / (1.0f + __expf(l[i1] - l[i0]));
        float w1 = 1.0f - w0;
        float* cwr = g_cw + warp * 4;
        cwr[0] = 0.f; cwr[1] = 0.f; cwr[2] = 0.f; cwr[3] = 0.f;
        cwr[i0] = w0;
        cwr[i1] = w1;
    }
}

// ---------------------------------------------------------------------------
// Routing: per (expert, token-block) compaction, deterministic block scan.
// ---------------------------------------------------------------------------
__global__ void route_kernel() {
    const int e   = blockIdx.x >> 2;
    const int tb  = blockIdx.x & 3;
    const int tid = threadIdx.x;
    const int t0  = tb * TB;

    int flags[4];
    int myc = 0;
    #pragma unroll
    for (int j = 0; j < 4; j++) {
        int t = t0 + tid * 4 + j;
        int f = (g_cw[t * 4 + e] > 0.f) ? 1 : 0;
        flags[j] = f;
        myc += f;
    }

    __shared__ int sc[256];
    sc[tid] = myc;
    __syncthreads();
    #pragma unroll
    for (int off = 1; off < 256; off <<= 1) {
        int v = (tid >= off) ? sc[tid - off] : 0;
        __syncthreads();
        sc[tid] += v;
        __syncthreads();
    }
    int pos = sc[tid] - myc;

    int* lst = g_route + (e * NTB + tb) * TB;
    #pragma unroll
    for (int j = 0; j < 4; j++) {
        if (flags[j]) lst[pos++] = t0 + tid * 4 + j;
    }
    if (tid == 255) g_cnt[e * NTB + tb] = sc[255];
}

// ---------------------------------------------------------------------------
// GEMM13 (routed, merged over tb via blockIdx.z):
// G[tb*TB+s,h] = tf32( cw[t,e] * silu(X[t]@W1)[h] * (X[t]@W3)[h] )
// BM=128, BN=64, BK=32; 2-stage cp.async; XOR-swizzled smem. 64KB dynamic.
// ---------------------------------------------------------------------------
#define G13_STAGE_WORDS 8192
#define G13_ITERS (DIM / 32)

__device__ __forceinline__ void g13_load_stage(
    uint32_t* sm, const int* toks, int s, int k0,
    const float* X, const float* W1, const float* W3,
    int tid, int bn)
{
    uint32_t* A  = sm + s * G13_STAGE_WORDS;
    uint32_t* B1 = A + 4096;
    uint32_t* B3 = A + 6144;
    #pragma unroll
    for (int i = 0; i < 4; i++) {
        int id  = tid + i * 256;
        int row = id >> 3;
        int c4  = (id & 7) * 4;
        cp16(A + row * 32 + (c4 ^ ((row & 7) * 4)),
             X + (size_t)toks[row] * DIM + k0 + c4);
    }
    #pragma unroll
    for (int i = 0; i < 2; i++) {
        int id  = tid + i * 256;
        int row = id >> 4;
        int c4  = (id & 15) * 4;
        int pc  = c4 ^ ((row & 3) * 8);
        size_t goff = (size_t)(k0 + row) * HID + bn + c4;
        cp16(B1 + row * 64 + pc, W1 + goff);
        cp16(B3 + row * 64 + pc, W3 + goff);
    }
    CP_COMMIT();
}

__global__ void __launch_bounds__(256, 2) gemm13_kernel(
    const float* __restrict__ X,
    const float* __restrict__ W1,
    const float* __restrict__ W3,
    int eidx)
{
    const int tb  = blockIdx.z;
    const int cnt = g_cnt[eidx * NTB + tb];
    const int bm  = blockIdx.y * 128;
    if (bm >= cnt) return;

    extern __shared__ __align__(16) uint32_t sm[];
    __shared__ int toks[128];

    const int tid  = threadIdx.x;
    const int bn   = blockIdx.x * 64;
    const int warp = tid >> 5;
    const int lane = tid & 31;
    const int wm   = (warp & 3) * 32;
    const int wn   = (warp >> 2) * 32;
    const int g    = lane >> 2;
    const int tig  = lane & 3;

    if (tid < 128) {
        int slot = bm + tid;
        if (slot >= cnt) slot = cnt - 1;
        toks[tid] = g_route[(eidx * NTB + tb) * TB + slot];
    }
    __syncthreads();

    float accA[2][4][4];
    float accB[2][4][4];
    #pragma unroll
    for (int mt = 0; mt < 2; mt++)
        #pragma unroll
        for (int nt = 0; nt < 4; nt++)
            #pragma unroll
            for (int i = 0; i < 4; i++) { accA[mt][nt][i] = 0.f; accB[mt][nt][i] = 0.f; }

    g13_load_stage(sm, toks, 0, 0, X, W1, W3, tid, bn);

    for (int it = 0; it < G13_ITERS; it++) {
        CP_WAIT0();
        __syncthreads();
        int s = it & 1;
        if (it + 1 < G13_ITERS)
            g13_load_stage(sm, toks, s ^ 1, (it + 1) * 32, X, W1, W3, tid, bn);

        const uint32_t* A  = sm + s * G13_STAGE_WORDS;
        const uint32_t* B1 = A + 4096;
        const uint32_t* B3 = A + 6144;

        #pragma unroll
        for (int kk = 0; kk < 32; kk += 8) {
            uint32_t a[2][4];
            const int xo = 4 * g;
            #pragma unroll
            for (int mt = 0; mt < 2; mt++) {
                int r = wm + mt * 16 + g;
                a[mt][0] = b2tf32(A[(size_t)r * 32 + ((kk + tig) ^ xo)]);
                a[mt][1] = b2tf32(A[(size_t)(r + 8) * 32 + ((kk + tig) ^ xo)]);
                a[mt][2] = b2tf32(A[(size_t)r * 32 + ((kk + tig + 4) ^ xo)]);
                a[mt][3] = b2tf32(A[(size_t)(r + 8) * 32 + ((kk + tig + 4) ^ xo)]);
            }
            const int krow = kk + tig;
            const int ko   = (krow & 3) * 8;
            #pragma unroll
            for (int nt = 0; nt < 4; nt++) {
                int n  = wn + nt * 8 + g;
                int pc = n ^ ko;
                uint32_t b1a = b2tf32(B1[krow * 64 + pc]);
                uint32_t b1b = b2tf32(B1[(krow + 4) * 64 + pc]);
                uint32_t b3a = b2tf32(B3[krow * 64 + pc]);
                uint32_t b3b = b2tf32(B3[(krow + 4) * 64 + pc]);
                #pragma unroll
                for (int mt = 0; mt < 2; mt++) {
                    mma8(accA[mt][nt], a[mt][0], a[mt][1], a[mt][2], a[mt][3], b1a, b1b);
                    mma8(accB[mt][nt], a[mt][0], a[mt][1], a[mt][2], a[mt][3], b3a, b3b);
                }
            }
        }
    }

    // epilogue: G[tb*TB + slot] = tf32(cw * silu(A) * B)
    #pragma unroll
    for (int mt = 0; mt < 2; mt++) {
        int lr0 = wm + mt * 16 + g;
        int lr1 = lr0 + 8;
        float cw0 = g_cw[toks[lr0] * 4 + eidx];
        float cw1 = g_cw[toks[lr1] * 4 + eidx];
        size_t r0 = (size_t)(tb * TB + bm + lr0) * HID;
        size_t r1 = (size_t)(tb * TB + bm + lr1) * HID;
        #pragma unroll
        for (int nt = 0; nt < 4; nt++) {
            int c = bn + wn + nt * 8 + 2 * tig;
            float v00 = silu_f(accA[mt][nt][0]) * accB[mt][nt][0] * cw0;
            float v01 = silu_f(accA[mt][nt][1]) * accB[mt][nt][1] * cw0;
            float v10 = silu_f(accA[mt][nt][2]) * accB[mt][nt][2] * cw1;
            float v11 = silu_f(accA[mt][nt][3]) * accB[mt][nt][3] * cw1;
            *(uint2*)&g_G[r0 + c] = make_uint2(f2tf32(v00), f2tf32(v01));
            *(uint2*)&g_G[r1 + c] = make_uint2(f2tf32(v10), f2tf32(v11));
        }
    }
}

// ---------------------------------------------------------------------------
// GEMM2 (routed, merged over tb): out[route[s],d] += (G[tb*TB+s,:] @ W2)[d]
// BM=64, BN=128, BK=32; 256 thr, 8 warps 2(m)x4(n), warp tile 32x32.
// A = g_G (tf32, zero cvt) via cp.async; B = W2 via cp.async, cvt on read.
// Stage = 2048 (A) + 4096 (B) = 6144 words; 2 stages = 48KB dynamic smem.
// Grid (8, 16, 4) = 512 CTAs, ~256 active after early-exit (~1 wave).
// ---------------------------------------------------------------------------
#define G2_STAGE_WORDS 6144
#define G2_ITERS (HID / 32)

__device__ __forceinline__ void g2_load_stage(
    uint32_t* smb, int s, int k0,
    const float* W2, int tid, int gm0, int bn)
{
    uint32_t* A = smb + s * G2_STAGE_WORDS;
    uint32_t* B = A + 2048;
    #pragma unroll
    for (int i = 0; i < 2; i++) {
        int id  = tid + i * 256;
        int row = id >> 3;
        int c4  = (id & 7) * 4;
        cp16(A + row * 32 + (c4 ^ ((row & 7) * 4)),
             g_G + (size_t)(gm0 + row) * HID + k0 + c4);
    }
    #pragma unroll
    for (int i = 0; i < 4; i++) {
        int id  = tid + i * 256;
        int row = id >> 5;
        int c4  = (id & 31) * 4;
        cp16(B + row * 128 + (c4 ^ ((row & 3) * 8)),
             W2 + (size_t)(k0 + row) * DIM + bn + c4);
    }
    CP_COMMIT();
}

__global__ void __launch_bounds__(256, 2) gemm2_kernel(
    const float* __restrict__ W2,
    float* __restrict__ out,
    int eidx)
{
    const int tb  = blockIdx.z;
    const int cnt = g_cnt[eidx * NTB + tb];
    const int bm  = blockIdx.y * 64;
    if (bm >= cnt) return;
    const int gm0 = tb * TB + bm;

    extern __shared__ __align__(16) uint32_t smd[];

    const int tid  = threadIdx.x;
    const int bn   = blockIdx.x * 128;
    const int warp = tid >> 5;
    const int lane = tid & 31;
    const int wm   = (warp & 1) * 32;
    const int wn   = (warp >> 1) * 32;
    const int g    = lane >> 2;
    const int tig  = lane & 3;

    float acc[2][4][4];
    #pragma unroll
    for (int mt = 0; mt < 2; mt++)
        #pragma unroll
        for (int nt = 0; nt < 4; nt++)
            #pragma unroll
            for (int i = 0; i < 4; i++) acc[mt][nt][i] = 0.f;

    g2_load_stage(smd, 0, 0, W2, tid, gm0, bn);

    for (int it = 0; it < G2_ITERS; it++) {
        CP_WAIT0();
        __syncthreads();
        int s = it & 1;
        if (it + 1 < G2_ITERS)
            g2_load_stage(smd, s ^ 1, (it + 1) * 32, W2, tid, gm0, bn);

        const uint32_t* A = smd + s * G2_STAGE_WORDS;
        const uint32_t* B = A + 2048;

        #pragma unroll
        for (int kk = 0; kk < 32; kk += 8) {
            uint32_t a[2][4];
            const int xo = 4 * g;
            #pragma unroll
            for (int mt = 0; mt < 2; mt++) {
                int r = wm + mt * 16 + g;
                a[mt][0] = A[(size_t)r * 32 + ((kk + tig) ^ xo)];
                a[mt][1] = A[(size_t)(r + 8) * 32 + ((kk + tig) ^ xo)];
                a[mt][2] = A[(size_t)r * 32 + ((kk + tig + 4) ^ xo)];
                a[mt][3] = A[(size_t)(r + 8) * 32 + ((kk + tig + 4) ^ xo)];
            }
            const int krow = kk + tig;
            const int ko   = (krow & 3) * 8;
            #pragma unroll
            for (int nt = 0; nt < 4; nt++) {
                int n  = wn + nt * 8 + g;
                int pc = n ^ ko;
                uint32_t b0 = b2tf32(B[krow * 128 + pc]);
                uint32_t b1 = b2tf32(B[(krow + 4) * 128 + pc]);
                #pragma unroll
                for (int mt = 0; mt < 2; mt++)
                    mma8(acc[mt][nt], a[mt][0], a[mt][1], a[mt][2], a[mt][3], b0, b1);
            }
        }
    }

    // epilogue: scatter-accumulate into out (guard rows >= cnt)
    const int* lst = g_route + (eidx * NTB + tb) * TB;
    #pragma unroll
    for (int mt = 0; mt < 2; mt++) {
        int lr0 = wm + mt * 16 + g;
        int lr1 = lr0 + 8;
        int s0 = bm + lr0;
        int s1 = bm + lr1;
        bool v0ok = s0 < cnt;
        bool v1ok = s1 < cnt;
        int t0 = v0ok ? lst[s0] : 0;
        int t1 = v1ok ? lst[s1] : 0;
        #pragma unroll
        for (int nt = 0; nt < 4; nt++) {
            int c = bn + wn + nt * 8 + 2 * tig;
            if (v0ok) {
                float2* p = (float2*)&out[(size_t)t0 * DIM + c];
                float2 o = *p;
                o.x += acc[mt][nt][0];
                o.y += acc[mt][nt][1];
                *p = o;
            }
            if (v1ok) {
                float2* p = (float2*)&out[(size_t)t1 * DIM + c];
                float2 o = *p;
                o.x += acc[mt][nt][2];
                o.y += acc[mt][nt][3];
                *p = o;
            }
        }
    }
}

// ---------------------------------------------------------------------------
extern "C" void kernel_launch(void* const* d_in, const int* in_sizes, int n_in,
                              void* d_out, int out_size) {
    const float* x   = (const float*)d_in[0];
    const float* gw  = (const float*)d_in[1];
    const float* w1  = (const float*)d_in[2];
    const float* w2  = (const float*)d_in[3];
    const float* w3  = (const float*)d_in[4];
    float* out = (float*)d_out;

    cudaFuncSetAttribute(gemm13_kernel,
                         cudaFuncAttributeMaxDynamicSharedMemorySize, 65536);
    cudaFuncSetAttribute(gemm2_kernel,
                         cudaFuncAttributeMaxDynamicSharedMemorySize, 49152);

    zero_out_kernel<<<(T_TOK * DIM) / (256 * 4), 256>>>((float4*)out);
    gate_kernel<<<T_TOK / 4, 128>>>(x, gw);
    route_kernel<<<EACT * NTB, 256>>>();

    for (int e = 0; e < EACT; e++) {
        const float* w1e = w1 + (size_t)e * DIM * HID;
        const float* w3e = w3 + (size_t)e * DIM * HID;
        const float* w2e = w2 + (size_t)e * HID * DIM;
        gemm13_kernel<<<dim3(HID / 64, TB / 128, NTB), 256, 65536>>>(x, w1e, w3e, e);
        gemm2_kernel<<<dim3(DIM / 128, TB / 64, NTB), 256, 49152>>>(w2e, out, e);
    }
}

// round 13
// speedup vs baseline: 2.9782x; 1.0792x over previous
#include <cuda_runtime.h>
#include <cstdint>

// Problem constants
#define T_TOK 4096
#define DIM   1024
#define HID   5632
#define EACT  4
#define TB    1024
#define NTB   (T_TOK / TB)

// Scratch: gates, routing, inverse map, per-expert G slabs, dense partials
__device__ float g_cw[T_TOK * EACT];
__device__ int   g_route[EACT * NTB * TB];
__device__ int   g_cnt[EACT * NTB];
__device__ int   g_slot[T_TOK * EACT];                       // -1 if not routed
__device__ __align__(16) uint32_t g_G[(size_t)EACT * T_TOK * HID];   // 368 MB
__device__ __align__(16) float    g_Y[(size_t)EACT * T_TOK * DIM];   // 67 MB

__device__ __forceinline__ uint32_t f2tf32(float f) {
    uint32_t r;
    asm("cvt.rna.tf32.f32 %0, %1;" : "=r"(r) : "f"(f));
    return r;
}
__device__ __forceinline__ uint32_t b2tf32(uint32_t b) {
    return f2tf32(__uint_as_float(b));
}

__device__ __forceinline__ void cp16(uint32_t* smem_ptr, const void* gptr) {
    uint32_t a = (uint32_t)__cvta_generic_to_shared(smem_ptr);
    asm volatile("cp.async.cg.shared.global [%0], [%1], 16;" :: "r"(a), "l"(gptr));
}
#define CP_COMMIT() asm volatile("cp.async.commit_group;")
#define CP_WAIT0()  asm volatile("cp.async.wait_group 0;")

__device__ __forceinline__ void mma8(float* c,
                                     uint32_t a0, uint32_t a1, uint32_t a2, uint32_t a3,
                                     uint32_t b0, uint32_t b1) {
    asm volatile(
        "mma.sync.aligned.m16n8k8.row.col.f32.tf32.tf32.f32 "
        "{%0,%1,%2,%3}, {%4,%5,%6,%7}, {%8,%9}, {%0,%1,%2,%3};\n"
        : "+f"(c[0]), "+f"(c[1]), "+f"(c[2]), "+f"(c[3])
        : "r"(a0), "r"(a1), "r"(a2), "r"(a3), "r"(b0), "r"(b1));
}

__device__ __forceinline__ float silu_f(float v) {
    return v / (1.0f + __expf(-v));
}

// ---------------------------------------------------------------------------
// Gate: one warp per token; experts 4..7 masked.
// ---------------------------------------------------------------------------
__global__ void gate_kernel(const float* __restrict__ x,
                            const float* __restrict__ gw) {
    int warp = (blockIdx.x * blockDim.x + threadIdx.x) >> 5;
    int lane = threadIdx.x & 31;
    if (warp >= T_TOK) return;

    const float* xr = x + (size_t)warp * DIM;
    float p0 = 0.f, p1 = 0.f, p2 = 0.f, p3 = 0.f;
    for (int d = lane; d < DIM; d += 32) {
        float xv = xr[d];
        p0 += xv * gw[0 * DIM + d];
        p1 += xv * gw[1 * DIM + d];
        p2 += xv * gw[2 * DIM + d];
        p3 += xv * gw[3 * DIM + d];
    }
    #pragma unroll
    for (int off = 16; off; off >>= 1) {
        p0 += __shfl_down_sync(0xffffffff, p0, off);
        p1 += __shfl_down_sync(0xffffffff, p1, off);
        p2 += __shfl_down_sync(0xffffffff, p2, off);
        p3 += __shfl_down_sync(0xffffffff, p3, off);
    }
    if (lane == 0) {
        float l[4] = {p0, p1, p2, p3};
        int i0 = 0;
        #pragma unroll
        for (int e = 1; e < 4; e++) if (l[e] > l[i0]) i0 = e;
        int i1 = -1;
        #pragma unroll
        for (int e = 0; e < 4; e++) {
            if (e == i0) continue;
            if (i1 < 0 || l[e] > l[i1]) i1 = e;
        }
        float w0 = 1.0f / (1.0f + __expf(l[i1] - l[i0]));
        float w1 = 1.0f - w0;
        float* cwr = g_cw + warp * 4;
        cwr[0] = 0.f; cwr[1] = 0.f; cwr[2] = 0.f; cwr[3] = 0.f;
        cwr[i0] = w0;
        cwr[i1] = w1;
    }
}

// ---------------------------------------------------------------------------
// Routing: per (expert, token-block) compaction + inverse map g_slot.
// ---------------------------------------------------------------------------
__global__ void route_kernel() {
    const int e   = blockIdx.x >> 2;
    const int tb  = blockIdx.x & 3;
    const int tid = threadIdx.x;
    const int t0  = tb * TB;

    int flags[4];
    int myc = 0;
    #pragma unroll
    for (int j = 0; j < 4; j++) {
        int t = t0 + tid * 4 + j;
        int f = (g_cw[t * 4 + e] > 0.f) ? 1 : 0;
        flags[j] = f;
        myc += f;
    }

    __shared__ int sc[256];
    sc[tid] = myc;
    __syncthreads();
    #pragma unroll
    for (int off = 1; off < 256; off <<= 1) {
        int v = (tid >= off) ? sc[tid - off] : 0;
        __syncthreads();
        sc[tid] += v;
        __syncthreads();
    }
    int pos = sc[tid] - myc;

    int* lst = g_route + (e * NTB + tb) * TB;
    #pragma unroll
    for (int j = 0; j < 4; j++) {
        int t = t0 + tid * 4 + j;
        if (flags[j]) {
            lst[pos] = t;
            g_slot[t * 4 + e] = pos;
            pos++;
        } else {
            g_slot[t * 4 + e] = -1;
        }
    }
    if (tid == 255) g_cnt[e * NTB + tb] = sc[255];
}

// ---------------------------------------------------------------------------
// GEMM13 (routed, merged over ALL experts: z = e*NTB+tb):
// G[e][tb*TB+s,h] = tf32( cw[t,e] * silu(X[t]@W1e)[h] * (X[t]@W3e)[h] )
// BM=128, BN=64, BK=32; 2-stage cp.async; XOR-swizzled smem. 64KB dynamic.
// ---------------------------------------------------------------------------
#define G13_STAGE_WORDS 8192
#define G13_ITERS (DIM / 32)

__device__ __forceinline__ void g13_load_stage(
    uint32_t* sm, const int* toks, int s, int k0,
    const float* X, const float* W1, const float* W3,
    int tid, int bn)
{
    uint32_t* A  = sm + s * G13_STAGE_WORDS;
    uint32_t* B1 = A + 4096;
    uint32_t* B3 = A + 6144;
    #pragma unroll
    for (int i = 0; i < 4; i++) {
        int id  = tid + i * 256;
        int row = id >> 3;
        int c4  = (id & 7) * 4;
        cp16(A + row * 32 + (c4 ^ ((row & 7) * 4)),
             X + (size_t)toks[row] * DIM + k0 + c4);
    }
    #pragma unroll
    for (int i = 0; i < 2; i++) {
        int id  = tid + i * 256;
        int row = id >> 4;
        int c4  = (id & 15) * 4;
        int pc  = c4 ^ ((row & 3) * 8);
        size_t goff = (size_t)(k0 + row) * HID + bn + c4;
        cp16(B1 + row * 64 + pc, W1 + goff);
        cp16(B3 + row * 64 + pc, W3 + goff);
    }
    CP_COMMIT();
}

__global__ void __launch_bounds__(256, 2) gemm13_kernel(
    const float* __restrict__ X,
    const float* __restrict__ w1,
    const float* __restrict__ w3)
{
    const int z    = blockIdx.z;
    const int eidx = z >> 2;
    const int tb   = z & 3;
    const int cnt  = g_cnt[z];
    const int bm   = blockIdx.y * 128;
    if (bm >= cnt) return;

    const float* W1 = w1 + (size_t)eidx * DIM * HID;
    const float* W3 = w3 + (size_t)eidx * DIM * HID;

    extern __shared__ __align__(16) uint32_t sm[];
    __shared__ int toks[128];

    const int tid  = threadIdx.x;
    const int bn   = blockIdx.x * 64;
    const int warp = tid >> 5;
    const int lane = tid & 31;
    const int wm   = (warp & 3) * 32;
    const int wn   = (warp >> 2) * 32;
    const int g    = lane >> 2;
    const int tig  = lane & 3;

    if (tid < 128) {
        int slot = bm + tid;
        if (slot >= cnt) slot = cnt - 1;
        toks[tid] = g_route[z * TB + slot];
    }
    __syncthreads();

    float accA[2][4][4];
    float accB[2][4][4];
    #pragma unroll
    for (int mt = 0; mt < 2; mt++)
        #pragma unroll
        for (int nt = 0; nt < 4; nt++)
            #pragma unroll
            for (int i = 0; i < 4; i++) { accA[mt][nt][i] = 0.f; accB[mt][nt][i] = 0.f; }

    g13_load_stage(sm, toks, 0, 0, X, W1, W3, tid, bn);

    for (int it = 0; it < G13_ITERS; it++) {
        CP_WAIT0();
        __syncthreads();
        int s = it & 1;
        if (it + 1 < G13_ITERS)
            g13_load_stage(sm, toks, s ^ 1, (it + 1) * 32, X, W1, W3, tid, bn);

        const uint32_t* A  = sm + s * G13_STAGE_WORDS;
        const uint32_t* B1 = A + 4096;
        const uint32_t* B3 = A + 6144;

        #pragma unroll
        for (int kk = 0; kk < 32; kk += 8) {
            uint32_t a[2][4];
            const int xo = 4 * g;
            #pragma unroll
            for (int mt = 0; mt < 2; mt++) {
                int r = wm + mt * 16 + g;
                a[mt][0] = b2tf32(A[(size_t)r * 32 + ((kk + tig) ^ xo)]);
                a[mt][1] = b2tf32(A[(size_t)(r + 8) * 32 + ((kk + tig) ^ xo)]);
                a[mt][2] = b2tf32(A[(size_t)r * 32 + ((kk + tig + 4) ^ xo)]);
                a[mt][3] = b2tf32(A[(size_t)(r + 8) * 32 + ((kk + tig + 4) ^ xo)]);
            }
            const int krow = kk + tig;
            const int ko   = (krow & 3) * 8;
            #pragma unroll
            for (int nt = 0; nt < 4; nt++) {
                int n  = wn + nt * 8 + g;
                int pc = n ^ ko;
                uint32_t b1a = b2tf32(B1[krow * 64 + pc]);
                uint32_t b1b = b2tf32(B1[(krow + 4) * 64 + pc]);
                uint32_t b3a = b2tf32(B3[krow * 64 + pc]);
                uint32_t b3b = b2tf32(B3[(krow + 4) * 64 + pc]);
                #pragma unroll
                for (int mt = 0; mt < 2; mt++) {
                    mma8(accA[mt][nt], a[mt][0], a[mt][1], a[mt][2], a[mt][3], b1a, b1b);
                    mma8(accB[mt][nt], a[mt][0], a[mt][1], a[mt][2], a[mt][3], b3a, b3b);
                }
            }
        }
    }

    // epilogue: G[z*TB + slot] = tf32(cw * silu(A) * B)
    #pragma unroll
    for (int mt = 0; mt < 2; mt++) {
        int lr0 = wm + mt * 16 + g;
        int lr1 = lr0 + 8;
        float cw0 = g_cw[toks[lr0] * 4 + eidx];
        float cw1 = g_cw[toks[lr1] * 4 + eidx];
        size_t r0 = ((size_t)z * TB + bm + lr0) * HID;
        size_t r1 = ((size_t)z * TB + bm + lr1) * HID;
        #pragma unroll
        for (int nt = 0; nt < 4; nt++) {
            int c = bn + wn + nt * 8 + 2 * tig;
            float v00 = silu_f(accA[mt][nt][0]) * accB[mt][nt][0] * cw0;
            float v01 = silu_f(accA[mt][nt][1]) * accB[mt][nt][1] * cw0;
            float v10 = silu_f(accA[mt][nt][2]) * accB[mt][nt][2] * cw1;
            float v11 = silu_f(accA[mt][nt][3]) * accB[mt][nt][3] * cw1;
            *(uint2*)&g_G[r0 + c] = make_uint2(f2tf32(v00), f2tf32(v01));
            *(uint2*)&g_G[r1 + c] = make_uint2(f2tf32(v10), f2tf32(v11));
        }
    }
}

// ---------------------------------------------------------------------------
// GEMM2 (merged over ALL experts): g_Y[z*TB+s,d] = (G[z*TB+s,:] @ W2e)[d]
// BM=64, BN=128, BK=32; 256 thr, 8 warps 2(m)x4(n), warp tile 32x32.
// Dense STG output (no scatter/RMW). 48KB dynamic smem.
// ---------------------------------------------------------------------------
#define G2_STAGE_WORDS 6144
#define G2_ITERS (HID / 32)

__device__ __forceinline__ void g2_load_stage(
    uint32_t* smb, int s, int k0,
    const float* W2, int tid, size_t gm0, int bn)
{
    uint32_t* A = smb + s * G2_STAGE_WORDS;
    uint32_t* B = A + 2048;
    #pragma unroll
    for (int i = 0; i < 2; i++) {
        int id  = tid + i * 256;
        int row = id >> 3;
        int c4  = (id & 7) * 4;
        cp16(A + row * 32 + (c4 ^ ((row & 7) * 4)),
             g_G + (gm0 + row) * HID + k0 + c4);
    }
    #pragma unroll
    for (int i = 0; i < 4; i++) {
        int id  = tid + i * 256;
        int row = id >> 5;
        int c4  = (id & 31) * 4;
        cp16(B + row * 128 + (c4 ^ ((row & 3) * 8)),
             W2 + (size_t)(k0 + row) * DIM + bn + c4);
    }
    CP_COMMIT();
}

__global__ void __launch_bounds__(256, 2) gemm2_kernel(
    const float* __restrict__ w2)
{
    const int z    = blockIdx.z;
    const int eidx = z >> 2;
    const int cnt  = g_cnt[z];
    const int bm   = blockIdx.y * 64;
    if (bm >= cnt) return;
    const size_t gm0 = (size_t)z * TB + bm;

    const float* W2 = w2 + (size_t)eidx * HID * DIM;

    extern __shared__ __align__(16) uint32_t smd[];

    const int tid  = threadIdx.x;
    const int bn   = blockIdx.x * 128;
    const int warp = tid >> 5;
    const int lane = tid & 31;
    const int wm   = (warp & 1) * 32;
    const int wn   = (warp >> 1) * 32;
    const int g    = lane >> 2;
    const int tig  = lane & 3;

    float acc[2][4][4];
    #pragma unroll
    for (int mt = 0; mt < 2; mt++)
        #pragma unroll
        for (int nt = 0; nt < 4; nt++)
            #pragma unroll
            for (int i = 0; i < 4; i++) acc[mt][nt][i] = 0.f;

    g2_load_stage(smd, 0, 0, W2, tid, gm0, bn);

    for (int it = 0; it < G2_ITERS; it++) {
        CP_WAIT0();
        __syncthreads();
        int s = it & 1;
        if (it + 1 < G2_ITERS)
            g2_load_stage(smd, s ^ 1, (it + 1) * 32, W2, tid, gm0, bn);

        const uint32_t* A = smd + s * G2_STAGE_WORDS;
        const uint32_t* B = A + 2048;

        #pragma unroll
        for (int kk = 0; kk < 32; kk += 8) {
            uint32_t a[2][4];
            const int xo = 4 * g;
            #pragma unroll
            for (int mt = 0; mt < 2; mt++) {
                int r = wm + mt * 16 + g;
                a[mt][0] = A[(size_t)r * 32 + ((kk + tig) ^ xo)];
                a[mt][1] = A[(size_t)(r + 8) * 32 + ((kk + tig) ^ xo)];
                a[mt][2] = A[(size_t)r * 32 + ((kk + tig + 4) ^ xo)];
                a[mt][3] = A[(size_t)(r + 8) * 32 + ((kk + tig + 4) ^ xo)];
            }
            const int krow = kk + tig;
            const int ko   = (krow & 3) * 8;
            #pragma unroll
            for (int nt = 0; nt < 4; nt++) {
                int n  = wn + nt * 8 + g;
                int pc = n ^ ko;
                uint32_t b0 = b2tf32(B[krow * 128 + pc]);
                uint32_t b1 = b2tf32(B[(krow + 4) * 128 + pc]);
                #pragma unroll
                for (int mt = 0; mt < 2; mt++)
                    mma8(acc[mt][nt], a[mt][0], a[mt][1], a[mt][2], a[mt][3], b0, b1);
            }
        }
    }

    // epilogue: dense store into g_Y (guard rows >= cnt)
    #pragma unroll
    for (int mt = 0; mt < 2; mt++) {
        int lr0 = wm + mt * 16 + g;
        int lr1 = lr0 + 8;
        bool v0ok = (bm + lr0) < cnt;
        bool v1ok = (bm + lr1) < cnt;
        float* y0 = g_Y + (gm0 + lr0) * DIM;
        float* y1 = g_Y + (gm0 + lr1) * DIM;
        #pragma unroll
        for (int nt = 0; nt < 4; nt++) {
            int c = bn + wn + nt * 8 + 2 * tig;
            if (v0ok) *(float2*)&y0[c] = make_float2(acc[mt][nt][0], acc[mt][nt][1]);
            if (v1ok) *(float2*)&y1[c] = make_float2(acc[mt][nt][2], acc[mt][nt][3]);
        }
    }
}

// ---------------------------------------------------------------------------
// Combine: out[t] = sum over experts with g_slot[t][e] >= 0 of g_Y row.
// One block per token; 256 threads x float4.
// ---------------------------------------------------------------------------
__global__ void combine_kernel(float* __restrict__ out) {
    const int t  = blockIdx.x;
    const int tb = t >> 10;           // t / TB
    const int d  = threadIdx.x * 4;

    float4 acc = make_float4(0.f, 0.f, 0.f, 0.f);
    #pragma unroll
    for (int e = 0; e < EACT; e++) {
        int slot = g_slot[t * 4 + e];
        if (slot >= 0) {
            const float4 v = *(const float4*)&g_Y[((size_t)(e * NTB + tb) * TB + slot) * DIM + d];
            acc.x += v.x; acc.y += v.y; acc.z += v.z; acc.w += v.w;
        }
    }
    *(float4*)&out[(size_t)t * DIM + d] = acc;
}

// ---------------------------------------------------------------------------
extern "C" void kernel_launch(void* const* d_in, const int* in_sizes, int n_in,
                              void* d_out, int out_size) {
    const float* x   = (const float*)d_in[0];
    const float* gw  = (const float*)d_in[1];
    const float* w1  = (const float*)d_in[2];
    const float* w2  = (const float*)d_in[3];
    const float* w3  = (const float*)d_in[4];
    float* out = (float*)d_out;

    cudaFuncSetAttribute(gemm13_kernel,
                         cudaFuncAttributeMaxDynamicSharedMemorySize, 65536);
    cudaFuncSetAttribute(gemm2_kernel,
                         cudaFuncAttributeMaxDynamicSharedMemorySize, 49152);

    gate_kernel<<<T_TOK / 4, 128>>>(x, gw);
    route_kernel<<<EACT * NTB, 256>>>();
    gemm13_kernel<<<dim3(HID / 64, TB / 128, EACT * NTB), 256, 65536>>>(x, w1, w3);
    gemm2_kernel<<<dim3(DIM / 128, TB / 64, EACT * NTB), 256, 49152>>>(w2);
    combine_kernel<<<T_TOK, 256>>>(out);
}

// round 16
// speedup vs baseline: 3.1031x; 1.0420x over previous
#include <cuda_runtime.h>
#include <cstdint>

// Problem constants
#define T_TOK 4096
#define DIM   1024
#define HID   5632
#define EACT  4
#define TB    1024
#define NTB   (T_TOK / TB)

// Scratch: gates, routing, inverse map, per-expert G slabs, dense partials
__device__ float g_cw[T_TOK * EACT];
__device__ int   g_route[EACT * NTB * TB];
__device__ int   g_cnt[EACT * NTB];
__device__ int   g_slot[T_TOK * EACT];                       // -1 if not routed
__device__ __align__(16) uint32_t g_G[(size_t)EACT * T_TOK * HID];   // 368 MB
__device__ __align__(16) float    g_Y[(size_t)EACT * T_TOK * DIM];   // 67 MB

__device__ __forceinline__ uint32_t f2tf32(float f) {
    uint32_t r;
    asm("cvt.rna.tf32.f32 %0, %1;" : "=r"(r) : "f"(f));
    return r;
}
__device__ __forceinline__ uint32_t b2tf32(uint32_t b) {
    return f2tf32(__uint_as_float(b));
}

__device__ __forceinline__ void cp16(uint32_t* smem_ptr, const void* gptr) {
    uint32_t a = (uint32_t)__cvta_generic_to_shared(smem_ptr);
    asm volatile("cp.async.cg.shared.global [%0], [%1], 16;" :: "r"(a), "l"(gptr));
}
#define CP_COMMIT() asm volatile("cp.async.commit_group;")
#define CP_WAIT0()  asm volatile("cp.async.wait_group 0;")
#define CP_WAIT1()  asm volatile("cp.async.wait_group 1;")

__device__ __forceinline__ void mma8(float* c,
                                     uint32_t a0, uint32_t a1, uint32_t a2, uint32_t a3,
                                     uint32_t b0, uint32_t b1) {
    asm volatile(
        "mma.sync.aligned.m16n8k8.row.col.f32.tf32.tf32.f32 "
        "{%0,%1,%2,%3}, {%4,%5,%6,%7}, {%8,%9}, {%0,%1,%2,%3};\n"
        : "+f"(c[0]), "+f"(c[1]), "+f"(c[2]), "+f"(c[3])
        : "r"(a0), "r"(a1), "r"(a2), "r"(a3), "r"(b0), "r"(b1));
}

__device__ __forceinline__ float silu_f(float v) {
    return v / (1.0f + __expf(-v));
}

// ---------------------------------------------------------------------------
// Gate: one warp per token; experts 4..7 masked.
// ---------------------------------------------------------------------------
__global__ void gate_kernel(const float* __restrict__ x,
                            const float* __restrict__ gw) {
    int warp = (blockIdx.x * blockDim.x + threadIdx.x) >> 5;
    int lane = threadIdx.x & 31;
    if (warp >= T_TOK) return;

    const float* xr = x + (size_t)warp * DIM;
    float p0 = 0.f, p1 = 0.f, p2 = 0.f, p3 = 0.f;
    for (int d = lane; d < DIM; d += 32) {
        float xv = xr[d];
        p0 += xv * gw[0 * DIM + d];
        p1 += xv * gw[1 * DIM + d];
        p2 += xv * gw[2 * DIM + d];
        p3 += xv * gw[3 * DIM + d];
    }
    #pragma unroll
    for (int off = 16; off; off >>= 1) {
        p0 += __shfl_down_sync(0xffffffff, p0, off);
        p1 += __shfl_down_sync(0xffffffff, p1, off);
        p2 += __shfl_down_sync(0xffffffff, p2, off);
        p3 += __shfl_down_sync(0xffffffff, p3, off);
    }
    if (lane == 0) {
        float l[4] = {p0, p1, p2, p3};
        int i0 = 0;
        #pragma unroll
        for (int e = 1; e < 4; e++) if (l[e] > l[i0]) i0 = e;
        int i1 = -1;
        #pragma unroll
        for (int e = 0; e < 4; e++) {
            if (e == i0) continue;
            if (i1 < 0 || l[e] > l[i1]) i1 = e;
        }
        float w0 = 1.0f / (1.0f + __expf(l[i1] - l[i0]));
        float w1 = 1.0f - w0;
        float* cwr = g_cw + warp * 4;
        cwr[0] = 0.f; cwr[1] = 0.f; cwr[2] = 0.f; cwr[3] = 0.f;
        cwr[i0] = w0;
        cwr[i1] = w1;
    }
}

// ---------------------------------------------------------------------------
// Routing: per (expert, token-block) compaction + inverse map g_slot.
// ---------------------------------------------------------------------------
__global__ void route_kernel() {
    const int e   = blockIdx.x >> 2;
    const int tb  = blockIdx.x & 3;
    const int tid = threadIdx.x;
    const int t0  = tb * TB;

    int flags[4];
    int myc = 0;
    #pragma unroll
    for (int j = 0; j < 4; j++) {
        int t = t0 + tid * 4 + j;
        int f = (g_cw[t * 4 + e] > 0.f) ? 1 : 0;
        flags[j] = f;
        myc += f;
    }

    __shared__ int sc[256];
    sc[tid] = myc;
    __syncthreads();
    #pragma unroll
    for (int off = 1; off < 256; off <<= 1) {
        int v = (tid >= off) ? sc[tid - off] : 0;
        __syncthreads();
        sc[tid] += v;
        __syncthreads();
    }
    int pos = sc[tid] - myc;

    int* lst = g_route + (e * NTB + tb) * TB;
    #pragma unroll
    for (int j = 0; j < 4; j++) {
        int t = t0 + tid * 4 + j;
        if (flags[j]) {
            lst[pos] = t;
            g_slot[t * 4 + e] = pos;
            pos++;
        } else {
            g_slot[t * 4 + e] = -1;
        }
    }
    if (tid == 255) g_cnt[e * NTB + tb] = sc[255];
}

// ---------------------------------------------------------------------------
// GEMM13 (routed, merged over ALL experts: z = e*NTB+tb):
// G[e][tb*TB+s,h] = tf32( cw[t,e] * silu(X[t]@W1e)[h] * (X[t]@W3e)[h] )
// BM=128, BN=64, BK=32; 3-stage cp.async (wait_group 1 steady / 0 on drain).
// Stage 32KB; 3 stages = 96KB dynamic smem.
// ---------------------------------------------------------------------------
#define G13_STAGE_WORDS 8192
#define G13_ITERS (DIM / 32)

__device__ __forceinline__ void g13_load_stage(
    uint32_t* sm, const int* toks, int s, int k0,
    const float* X, const float* W1, const float* W3,
    int tid, int bn)
{
    uint32_t* A  = sm + s * G13_STAGE_WORDS;
    uint32_t* B1 = A + 4096;
    uint32_t* B3 = A + 6144;
    #pragma unroll
    for (int i = 0; i < 4; i++) {
        int id  = tid + i * 256;
        int row = id >> 3;
        int c4  = (id & 7) * 4;
        cp16(A + row * 32 + (c4 ^ ((row & 7) * 4)),
             X + (size_t)toks[row] * DIM + k0 + c4);
    }
    #pragma unroll
    for (int i = 0; i < 2; i++) {
        int id  = tid + i * 256;
        int row = id >> 4;
        int c4  = (id & 15) * 4;
        int pc  = c4 ^ ((row & 3) * 8);
        size_t goff = (size_t)(k0 + row) * HID + bn + c4;
        cp16(B1 + row * 64 + pc, W1 + goff);
        cp16(B3 + row * 64 + pc, W3 + goff);
    }
    CP_COMMIT();
}

__global__ void __launch_bounds__(256, 2) gemm13_kernel(
    const float* __restrict__ X,
    const float* __restrict__ w1,
    const float* __restrict__ w3)
{
    const int z    = blockIdx.z;
    const int eidx = z >> 2;
    const int cnt  = g_cnt[z];
    const int bm   = blockIdx.y * 128;
    if (bm >= cnt) return;

    const float* W1 = w1 + (size_t)eidx * DIM * HID;
    const float* W3 = w3 + (size_t)eidx * DIM * HID;

    extern __shared__ __align__(16) uint32_t sm[];
    __shared__ int toks[128];

    const int tid  = threadIdx.x;
    const int bn   = blockIdx.x * 64;
    const int warp = tid >> 5;
    const int lane = tid & 31;
    const int wm   = (warp & 3) * 32;
    const int wn   = (warp >> 2) * 32;
    const int g    = lane >> 2;
    const int tig  = lane & 3;

    if (tid < 128) {
        int slot = bm + tid;
        if (slot >= cnt) slot = cnt - 1;
        toks[tid] = g_route[z * TB + slot];
    }
    __syncthreads();

    float accA[2][4][4];
    float accB[2][4][4];
    #pragma unroll
    for (int mt = 0; mt < 2; mt++)
        #pragma unroll
        for (int nt = 0; nt < 4; nt++)
            #pragma unroll
            for (int i = 0; i < 4; i++) { accA[mt][nt][i] = 0.f; accB[mt][nt][i] = 0.f; }

    g13_load_stage(sm, toks, 0, 0, X, W1, W3, tid, bn);
    g13_load_stage(sm, toks, 1, 32, X, W1, W3, tid, bn);

    int s = 0, sload = 2;
    for (int it = 0; it < G13_ITERS; it++) {
        // Steady state: 2 groups in flight (it, it+1); WAIT1 completes group(it).
        // Drain (no load issued at it-1): only 1 group pending -> must WAIT0.
        if (it + 2 < G13_ITERS) CP_WAIT1(); else CP_WAIT0();
        __syncthreads();
        if (it + 2 < G13_ITERS) {
            g13_load_stage(sm, toks, sload, (it + 2) * 32, X, W1, W3, tid, bn);
            if (++sload == 3) sload = 0;
        }

        const uint32_t* A  = sm + s * G13_STAGE_WORDS;
        const uint32_t* B1 = A + 4096;
        const uint32_t* B3 = A + 6144;
        if (++s == 3) s = 0;

        #pragma unroll
        for (int kk = 0; kk < 32; kk += 8) {
            uint32_t a[2][4];
            const int xo = 4 * g;
            #pragma unroll
            for (int mt = 0; mt < 2; mt++) {
                int r = wm + mt * 16 + g;
                a[mt][0] = b2tf32(A[(size_t)r * 32 + ((kk + tig) ^ xo)]);
                a[mt][1] = b2tf32(A[(size_t)(r + 8) * 32 + ((kk + tig) ^ xo)]);
                a[mt][2] = b2tf32(A[(size_t)r * 32 + ((kk + tig + 4) ^ xo)]);
                a[mt][3] = b2tf32(A[(size_t)(r + 8) * 32 + ((kk + tig + 4) ^ xo)]);
            }
            const int krow = kk + tig;
            const int ko   = (krow & 3) * 8;
            #pragma unroll
            for (int nt = 0; nt < 4; nt++) {
                int n  = wn + nt * 8 + g;
                int pc = n ^ ko;
                uint32_t b1a = b2tf32(B1[krow * 64 + pc]);
                uint32_t b1b = b2tf32(B1[(krow + 4) * 64 + pc]);
                uint32_t b3a = b2tf32(B3[krow * 64 + pc]);
                uint32_t b3b = b2tf32(B3[(krow + 4) * 64 + pc]);
                #pragma unroll
                for (int mt = 0; mt < 2; mt++) {
                    mma8(accA[mt][nt], a[mt][0], a[mt][1], a[mt][2], a[mt][3], b1a, b1b);
                    mma8(accB[mt][nt], a[mt][0], a[mt][1], a[mt][2], a[mt][3], b3a, b3b);
                }
            }
        }
    }

    // epilogue: G[z*TB + slot] = tf32(cw * silu(A) * B)
    #pragma unroll
    for (int mt = 0; mt < 2; mt++) {
        int lr0 = wm + mt * 16 + g;
        int lr1 = lr0 + 8;
        float cw0 = g_cw[toks[lr0] * 4 + eidx];
        float cw1 = g_cw[toks[lr1] * 4 + eidx];
        size_t r0 = ((size_t)z * TB + bm + lr0) * HID;
        size_t r1 = ((size_t)z * TB + bm + lr1) * HID;
        #pragma unroll
        for (int nt = 0; nt < 4; nt++) {
            int c = bn + wn + nt * 8 + 2 * tig;
            float v00 = silu_f(accA[mt][nt][0]) * accB[mt][nt][0] * cw0;
            float v01 = silu_f(accA[mt][nt][1]) * accB[mt][nt][1] * cw0;
            float v10 = silu_f(accA[mt][nt][2]) * accB[mt][nt][2] * cw1;
            float v11 = silu_f(accA[mt][nt][3]) * accB[mt][nt][3] * cw1;
            *(uint2*)&g_G[r0 + c] = make_uint2(f2tf32(v00), f2tf32(v01));
            *(uint2*)&g_G[r1 + c] = make_uint2(f2tf32(v10), f2tf32(v11));
        }
    }
}

// ---------------------------------------------------------------------------
// GEMM2 (merged over ALL experts): g_Y[z*TB+s,d] = (G[z*TB+s,:] @ W2e)[d]
// BM=64, BN=128, BK=64; 256 thr, 8 warps 2(m)x4(n), warp tile 32x32.
// 2-stage cp.async (WAIT0); stage 48KB; 96KB dynamic smem. Dense STG output.
// ---------------------------------------------------------------------------
#define G2_STAGE_WORDS 12288
#define G2_ITERS (HID / 64)

__device__ __forceinline__ void g2_load_stage(
    uint32_t* smb, int s, int k0,
    const float* W2, int tid, size_t gm0, int bn)
{
    uint32_t* A = smb + s * G2_STAGE_WORDS;
    uint32_t* B = A + 4096;
    #pragma unroll
    for (int i = 0; i < 4; i++) {
        int id  = tid + i * 256;
        int row = id >> 4;             // 64 rows x 16 float4/row
        int c4  = (id & 15) * 4;
        cp16(A + row * 64 + (c4 ^ ((row & 7) * 4)),
             g_G + (gm0 + row) * HID + k0 + c4);
    }
    #pragma unroll
    for (int i = 0; i < 8; i++) {
        int id  = tid + i * 256;
        int row = id >> 5;             // 64 rows x 32 float4/row
        int c4  = (id & 31) * 4;
        cp16(B + row * 128 + (c4 ^ ((row & 3) * 8)),
             W2 + (size_t)(k0 + row) * DIM + bn + c4);
    }
    CP_COMMIT();
}

__global__ void __launch_bounds__(256, 2) gemm2_kernel(
    const float* __restrict__ w2)
{
    const int z    = blockIdx.z;
    const int eidx = z >> 2;
    const int cnt  = g_cnt[z];
    const int bm   = blockIdx.y * 64;
    if (bm >= cnt) return;
    const size_t gm0 = (size_t)z * TB + bm;

    const float* W2 = w2 + (size_t)eidx * HID * DIM;

    extern __shared__ __align__(16) uint32_t smd[];

    const int tid  = threadIdx.x;
    const int bn   = blockIdx.x * 128;
    const int warp = tid >> 5;
    const int lane = tid & 31;
    const int wm   = (warp & 1) * 32;
    const int wn   = (warp >> 1) * 32;
    const int g    = lane >> 2;
    const int tig  = lane & 3;

    float acc[2][4][4];
    #pragma unroll
    for (int mt = 0; mt < 2; mt++)
        #pragma unroll
        for (int nt = 0; nt < 4; nt++)
            #pragma unroll
            for (int i = 0; i < 4; i++) acc[mt][nt][i] = 0.f;

    g2_load_stage(smd, 0, 0, W2, tid, gm0, bn);

    for (int it = 0; it < G2_ITERS; it++) {
        CP_WAIT0();
        __syncthreads();
        int s = it & 1;
        if (it + 1 < G2_ITERS)
            g2_load_stage(smd, s ^ 1, (it + 1) * 64, W2, tid, gm0, bn);

        const uint32_t* A = smd + s * G2_STAGE_WORDS;
        const uint32_t* B = A + 4096;

        #pragma unroll
        for (int kk = 0; kk < 64; kk += 8) {
            uint32_t a[2][4];
            const int xo = 4 * g;
            #pragma unroll
            for (int mt = 0; mt < 2; mt++) {
                int r = wm + mt * 16 + g;
                a[mt][0] = A[(size_t)r * 64 + ((kk + tig) ^ xo)];
                a[mt][1] = A[(size_t)(r + 8) * 64 + ((kk + tig) ^ xo)];
                a[mt][2] = A[(size_t)r * 64 + ((kk + tig + 4) ^ xo)];
                a[mt][3] = A[(size_t)(r + 8) * 64 + ((kk + tig + 4) ^ xo)];
            }
            const int krow = kk + tig;
            const int ko   = (krow & 3) * 8;
            #pragma unroll
            for (int nt = 0; nt < 4; nt++) {
                int n  = wn + nt * 8 + g;
                int pc = n ^ ko;
                uint32_t b0 = b2tf32(B[krow * 128 + pc]);
                uint32_t b1 = b2tf32(B[(krow + 4) * 128 + pc]);
                #pragma unroll
                for (int mt = 0; mt < 2; mt++)
                    mma8(acc[mt][nt], a[mt][0], a[mt][1], a[mt][2], a[mt][3], b0, b1);
            }
        }
    }

    // epilogue: dense store into g_Y (guard rows >= cnt)
    #pragma unroll
    for (int mt = 0; mt < 2; mt++) {
        int lr0 = wm + mt * 16 + g;
        int lr1 = lr0 + 8;
        bool v0ok = (bm + lr0) < cnt;
        bool v1ok = (bm + lr1) < cnt;
        float* y0 = g_Y + (gm0 + lr0) * DIM;
        float* y1 = g_Y + (gm0 + lr1) * DIM;
        #pragma unroll
        for (int nt = 0; nt < 4; nt++) {
            int c = bn + wn + nt * 8 + 2 * tig;
            if (v0ok) *(float2*)&y0[c] = make_float2(acc[mt][nt][0], acc[mt][nt][1]);
            if (v1ok) *(float2*)&y1[c] = make_float2(acc[mt][nt][2], acc[mt][nt][3]);
        }
    }
}

// ---------------------------------------------------------------------------
// Combine: out[t] = sum over experts with g_slot[t][e] >= 0 of g_Y row.
// ---------------------------------------------------------------------------
__global__ void combine_kernel(float* __restrict__ out) {
    const int t  = blockIdx.x;
    const int tb = t >> 10;
    const int d  = threadIdx.x * 4;

    float4 acc = make_float4(0.f, 0.f, 0.f, 0.f);
    #pragma unroll
    for (int e = 0; e < EACT; e++) {
        int slot = g_slot[t * 4 + e];
        if (slot >= 0) {
            const float4 v = *(const float4*)&g_Y[((size_t)(e * NTB + tb) * TB + slot) * DIM + d];
            acc.x += v.x; acc.y += v.y; acc.z += v.z; acc.w += v.w;
        }
    }
    *(float4*)&out[(size_t)t * DIM + d] = acc;
}

// ---------------------------------------------------------------------------
extern "C" void kernel_launch(void* const* d_in, const int* in_sizes, int n_in,
                              void* d_out, int out_size) {
    const float* x   = (const float*)d_in[0];
    const float* gw  = (const float*)d_in[1];
    const float* w1  = (const float*)d_in[2];
    const float* w2  = (const float*)d_in[3];
    const float* w3  = (const float*)d_in[4];
    float* out = (float*)d_out;

    cudaFuncSetAttribute(gemm13_kernel,
                         cudaFuncAttributeMaxDynamicSharedMemorySize, 3 * G13_STAGE_WORDS * 4);
    cudaFuncSetAttribute(gemm2_kernel,
                         cudaFuncAttributeMaxDynamicSharedMemorySize, 2 * G2_STAGE_WORDS * 4);

    gate_kernel<<<T_TOK / 4, 128>>>(x, gw);
    route_kernel<<<EACT * NTB, 256>>>();
    gemm13_kernel<<<dim3(HID / 64, TB / 128, EACT * NTB), 256, 3 * G13_STAGE_WORDS * 4>>>(x, w1, w3);
    gemm2_kernel<<<dim3(DIM / 128, TB / 64, EACT * NTB), 256, 2 * G2_STAGE_WORDS * 4>>>(w2);
    combine_kernel<<<T_TOK, 256>>>(out);
}

// round 17
// speedup vs baseline: 3.2680x; 1.0531x over previous
#include <cuda_runtime.h>
#include <cstdint>

// Problem constants
#define T_TOK 4096
#define DIM   1024
#define HID   5632
#define EACT  4
#define TB    1024
#define NTB   (T_TOK / TB)

// Scratch: gates, routing, inverse map, tf32 operand copies, G slabs, partials
__device__ float g_cw[T_TOK * EACT];
__device__ int   g_route[EACT * NTB * TB];
__device__ int   g_cnt[EACT * NTB];
__device__ int   g_slot[T_TOK * EACT];
__device__ __align__(16) uint32_t g_Xt[(size_t)T_TOK * DIM];           // 16 MB
__device__ __align__(16) uint32_t g_W1t[(size_t)EACT * DIM * HID];     // 92 MB
__device__ __align__(16) uint32_t g_W3t[(size_t)EACT * DIM * HID];     // 92 MB
__device__ __align__(16) uint32_t g_W2t[(size_t)EACT * HID * DIM];     // 92 MB
__device__ __align__(16) uint32_t g_G[(size_t)EACT * T_TOK * HID];     // 368 MB
__device__ __align__(16) float    g_Y[(size_t)EACT * T_TOK * DIM];     // 67 MB

__device__ __forceinline__ uint32_t f2tf32(float f) {
    uint32_t r;
    asm("cvt.rna.tf32.f32 %0, %1;" : "=r"(r) : "f"(f));
    return r;
}

__device__ __forceinline__ void cp16(uint32_t* smem_ptr, const void* gptr) {
    uint32_t a = (uint32_t)__cvta_generic_to_shared(smem_ptr);
    asm volatile("cp.async.cg.shared.global [%0], [%1], 16;" :: "r"(a), "l"(gptr));
}
#define CP_COMMIT() asm volatile("cp.async.commit_group;")
#define CP_WAIT0()  asm volatile("cp.async.wait_group 0;")
#define CP_WAIT1()  asm volatile("cp.async.wait_group 1;")

__device__ __forceinline__ void mma8(float* c,
                                     uint32_t a0, uint32_t a1, uint32_t a2, uint32_t a3,
                                     uint32_t b0, uint32_t b1) {
    asm volatile(
        "mma.sync.aligned.m16n8k8.row.col.f32.tf32.tf32.f32 "
        "{%0,%1,%2,%3}, {%4,%5,%6,%7}, {%8,%9}, {%0,%1,%2,%3};\n"
        : "+f"(c[0]), "+f"(c[1]), "+f"(c[2]), "+f"(c[3])
        : "r"(a0), "r"(a1), "r"(a2), "r"(a3), "r"(b0), "r"(b1));
}

__device__ __forceinline__ float silu_f(float v) {
    return v / (1.0f + __expf(-v));
}

// ---------------------------------------------------------------------------
// Convert f32 -> tf32 bits, float4-vectorized, grid-stride.
// ---------------------------------------------------------------------------
__global__ void cvt4_kernel(const float4* __restrict__ src,
                            uint4* __restrict__ dst, size_t n4) {
    size_t i = (size_t)blockIdx.x * blockDim.x + threadIdx.x;
    size_t stride = (size_t)gridDim.x * blockDim.x;
    for (; i < n4; i += stride) {
        float4 v = src[i];
        dst[i] = make_uint4(f2tf32(v.x), f2tf32(v.y), f2tf32(v.z), f2tf32(v.w));
    }
}

// ---------------------------------------------------------------------------
// Gate: one warp per token; experts 4..7 masked.
// ---------------------------------------------------------------------------
__global__ void gate_kernel(const float* __restrict__ x,
                            const float* __restrict__ gw) {
    int warp = (blockIdx.x * blockDim.x + threadIdx.x) >> 5;
    int lane = threadIdx.x & 31;
    if (warp >= T_TOK) return;

    const float* xr = x + (size_t)warp * DIM;
    float p0 = 0.f, p1 = 0.f, p2 = 0.f, p3 = 0.f;
    for (int d = lane; d < DIM; d += 32) {
        float xv = xr[d];
        p0 += xv * gw[0 * DIM + d];
        p1 += xv * gw[1 * DIM + d];
        p2 += xv * gw[2 * DIM + d];
        p3 += xv * gw[3 * DIM + d];
    }
    #pragma unroll
    for (int off = 16; off; off >>= 1) {
        p0 += __shfl_down_sync(0xffffffff, p0, off);
        p1 += __shfl_down_sync(0xffffffff, p1, off);
        p2 += __shfl_down_sync(0xffffffff, p2, off);
        p3 += __shfl_down_sync(0xffffffff, p3, off);
    }
    if (lane == 0) {
        float l[4] = {p0, p1, p2, p3};
        int i0 = 0;
        #pragma unroll
        for (int e = 1; e < 4; e++) if (l[e] > l[i0]) i0 = e;
        int i1 = -1;
        #pragma unroll
        for (int e = 0; e < 4; e++) {
            if (e == i0) continue;
            if (i1 < 0 || l[e] > l[i1]) i1 = e;
        }
        float w0 = 1.0f / (1.0f + __expf(l[i1] - l[i0]));
        float w1 = 1.0f - w0;
        float* cwr = g_cw + warp * 4;
        cwr[0] = 0.f; cwr[1] = 0.f; cwr[2] = 0.f; cwr[3] = 0.f;
        cwr[i0] = w0;
        cwr[i1] = w1;
    }
}

// ---------------------------------------------------------------------------
// Routing: per (expert, token-block) compaction + inverse map g_slot.
// ---------------------------------------------------------------------------
__global__ void route_kernel() {
    const int e   = blockIdx.x >> 2;
    const int tb  = blockIdx.x & 3;
    const int tid = threadIdx.x;
    const int t0  = tb * TB;

    int flags[4];
    int myc = 0;
    #pragma unroll
    for (int j = 0; j < 4; j++) {
        int t = t0 + tid * 4 + j;
        int f = (g_cw[t * 4 + e] > 0.f) ? 1 : 0;
        flags[j] = f;
        myc += f;
    }

    __shared__ int sc[256];
    sc[tid] = myc;
    __syncthreads();
    #pragma unroll
    for (int off = 1; off < 256; off <<= 1) {
        int v = (tid >= off) ? sc[tid - off] : 0;
        __syncthreads();
        sc[tid] += v;
        __syncthreads();
    }
    int pos = sc[tid] - myc;

    int* lst = g_route + (e * NTB + tb) * TB;
    #pragma unroll
    for (int j = 0; j < 4; j++) {
        int t = t0 + tid * 4 + j;
        if (flags[j]) {
            lst[pos] = t;
            g_slot[t * 4 + e] = pos;
            pos++;
        } else {
            g_slot[t * 4 + e] = -1;
        }
    }
    if (tid == 255) g_cnt[e * NTB + tb] = sc[255];
}

// ---------------------------------------------------------------------------
// GEMM13 (routed, merged over ALL experts: z = e*NTB+tb):
// All operands pre-converted tf32 bits -> inner loop has ZERO cvts.
// BM=128, BN=64, BK=32; 3-stage cp.async (WAIT1 steady / WAIT0 drain).
// ---------------------------------------------------------------------------
#define G13_STAGE_WORDS 8192
#define G13_ITERS (DIM / 32)

__device__ __forceinline__ void g13_load_stage(
    uint32_t* sm, const int* toks, int s, int k0,
    const uint32_t* W1, const uint32_t* W3,
    int tid, int bn)
{
    uint32_t* A  = sm + s * G13_STAGE_WORDS;
    uint32_t* B1 = A + 4096;
    uint32_t* B3 = A + 6144;
    #pragma unroll
    for (int i = 0; i < 4; i++) {
        int id  = tid + i * 256;
        int row = id >> 3;
        int c4  = (id & 7) * 4;
        cp16(A + row * 32 + (c4 ^ ((row & 7) * 4)),
             g_Xt + (size_t)toks[row] * DIM + k0 + c4);
    }
    #pragma unroll
    for (int i = 0; i < 2; i++) {
        int id  = tid + i * 256;
        int row = id >> 4;
        int c4  = (id & 15) * 4;
        int pc  = c4 ^ ((row & 3) * 8);
        size_t goff = (size_t)(k0 + row) * HID + bn + c4;
        cp16(B1 + row * 64 + pc, W1 + goff);
        cp16(B3 + row * 64 + pc, W3 + goff);
    }
    CP_COMMIT();
}

__global__ void __launch_bounds__(256, 2) gemm13_kernel()
{
    const int z    = blockIdx.z;
    const int eidx = z >> 2;
    const int cnt  = g_cnt[z];
    const int bm   = blockIdx.y * 128;
    if (bm >= cnt) return;

    const uint32_t* W1 = g_W1t + (size_t)eidx * DIM * HID;
    const uint32_t* W3 = g_W3t + (size_t)eidx * DIM * HID;

    extern __shared__ __align__(16) uint32_t sm[];
    __shared__ int toks[128];

    const int tid  = threadIdx.x;
    const int bn   = blockIdx.x * 64;
    const int warp = tid >> 5;
    const int lane = tid & 31;
    const int wm   = (warp & 3) * 32;
    const int wn   = (warp >> 2) * 32;
    const int g    = lane >> 2;
    const int tig  = lane & 3;

    if (tid < 128) {
        int slot = bm + tid;
        if (slot >= cnt) slot = cnt - 1;
        toks[tid] = g_route[z * TB + slot];
    }
    __syncthreads();

    float accA[2][4][4];
    float accB[2][4][4];
    #pragma unroll
    for (int mt = 0; mt < 2; mt++)
        #pragma unroll
        for (int nt = 0; nt < 4; nt++)
            #pragma unroll
            for (int i = 0; i < 4; i++) { accA[mt][nt][i] = 0.f; accB[mt][nt][i] = 0.f; }

    g13_load_stage(sm, toks, 0, 0, W1, W3, tid, bn);
    g13_load_stage(sm, toks, 1, 32, W1, W3, tid, bn);

    int s = 0, sload = 2;
    for (int it = 0; it < G13_ITERS; it++) {
        if (it + 2 < G13_ITERS) CP_WAIT1(); else CP_WAIT0();
        __syncthreads();
        if (it + 2 < G13_ITERS) {
            g13_load_stage(sm, toks, sload, (it + 2) * 32, W1, W3, tid, bn);
            if (++sload == 3) sload = 0;
        }

        const uint32_t* A  = sm + s * G13_STAGE_WORDS;
        const uint32_t* B1 = A + 4096;
        const uint32_t* B3 = A + 6144;
        if (++s == 3) s = 0;

        #pragma unroll
        for (int kk = 0; kk < 32; kk += 8) {
            uint32_t a[2][4];
            const int xo = 4 * g;
            #pragma unroll
            for (int mt = 0; mt < 2; mt++) {
                int r = wm + mt * 16 + g;
                a[mt][0] = A[(size_t)r * 32 + ((kk + tig) ^ xo)];
                a[mt][1] = A[(size_t)(r + 8) * 32 + ((kk + tig) ^ xo)];
                a[mt][2] = A[(size_t)r * 32 + ((kk + tig + 4) ^ xo)];
                a[mt][3] = A[(size_t)(r + 8) * 32 + ((kk + tig + 4) ^ xo)];
            }
            const int krow = kk + tig;
            const int ko   = (krow & 3) * 8;
            #pragma unroll
            for (int nt = 0; nt < 4; nt++) {
                int n  = wn + nt * 8 + g;
                int pc = n ^ ko;
                uint32_t b1a = B1[krow * 64 + pc];
                uint32_t b1b = B1[(krow + 4) * 64 + pc];
                uint32_t b3a = B3[krow * 64 + pc];
                uint32_t b3b = B3[(krow + 4) * 64 + pc];
                #pragma unroll
                for (int mt = 0; mt < 2; mt++) {
                    mma8(accA[mt][nt], a[mt][0], a[mt][1], a[mt][2], a[mt][3], b1a, b1b);
                    mma8(accB[mt][nt], a[mt][0], a[mt][1], a[mt][2], a[mt][3], b3a, b3b);
                }
            }
        }
    }

    // epilogue: G[z*TB + slot] = tf32(cw * silu(A) * B)
    #pragma unroll
    for (int mt = 0; mt < 2; mt++) {
        int lr0 = wm + mt * 16 + g;
        int lr1 = lr0 + 8;
        float cw0 = g_cw[toks[lr0] * 4 + eidx];
        float cw1 = g_cw[toks[lr1] * 4 + eidx];
        size_t r0 = ((size_t)z * TB + bm + lr0) * HID;
        size_t r1 = ((size_t)z * TB + bm + lr1) * HID;
        #pragma unroll
        for (int nt = 0; nt < 4; nt++) {
            int c = bn + wn + nt * 8 + 2 * tig;
            float v00 = silu_f(accA[mt][nt][0]) * accB[mt][nt][0] * cw0;
            float v01 = silu_f(accA[mt][nt][1]) * accB[mt][nt][1] * cw0;
            float v10 = silu_f(accA[mt][nt][2]) * accB[mt][nt][2] * cw1;
            float v11 = silu_f(accA[mt][nt][3]) * accB[mt][nt][3] * cw1;
            *(uint2*)&g_G[r0 + c] = make_uint2(f2tf32(v00), f2tf32(v01));
            *(uint2*)&g_G[r1 + c] = make_uint2(f2tf32(v10), f2tf32(v11));
        }
    }
}

// ---------------------------------------------------------------------------
// GEMM2 (merged): g_Y[z*TB+s,d] = (G[z*TB+s,:] @ W2e)[d]; zero cvts.
// BM=64, BN=128, BK=64; 2-stage cp.async; 96KB dynamic smem.
// ---------------------------------------------------------------------------
#define G2_STAGE_WORDS 12288
#define G2_ITERS (HID / 64)

__device__ __forceinline__ void g2_load_stage(
    uint32_t* smb, int s, int k0,
    const uint32_t* W2, int tid, size_t gm0, int bn)
{
    uint32_t* A = smb + s * G2_STAGE_WORDS;
    uint32_t* B = A + 4096;
    #pragma unroll
    for (int i = 0; i < 4; i++) {
        int id  = tid + i * 256;
        int row = id >> 4;
        int c4  = (id & 15) * 4;
        cp16(A + row * 64 + (c4 ^ ((row & 7) * 4)),
             g_G + (gm0 + row) * HID + k0 + c4);
    }
    #pragma unroll
    for (int i = 0; i < 8; i++) {
        int id  = tid + i * 256;
        int row = id >> 5;
        int c4  = (id & 31) * 4;
        cp16(B + row * 128 + (c4 ^ ((row & 3) * 8)),
             W2 + (size_t)(k0 + row) * DIM + bn + c4);
    }
    CP_COMMIT();
}

__global__ void __launch_bounds__(256, 2) gemm2_kernel()
{
    const int z    = blockIdx.z;
    const int eidx = z >> 2;
    const int cnt  = g_cnt[z];
    const int bm   = blockIdx.y * 64;
    if (bm >= cnt) return;
    const size_t gm0 = (size_t)z * TB + bm;

    const uint32_t* W2 = g_W2t + (size_t)eidx * HID * DIM;

    extern __shared__ __align__(16) uint32_t smd[];

    const int tid  = threadIdx.x;
    const int bn   = blockIdx.x * 128;
    const int warp = tid >> 5;
    const int lane = tid & 31;
    const int wm   = (warp & 1) * 32;
    const int wn   = (warp >> 1) * 32;
    const int g    = lane >> 2;
    const int tig  = lane & 3;

    float acc[2][4][4];
    #pragma unroll
    for (int mt = 0; mt < 2; mt++)
        #pragma unroll
        for (int nt = 0; nt < 4; nt++)
            #pragma unroll
            for (int i = 0; i < 4; i++) acc[mt][nt][i] = 0.f;

    g2_load_stage(smd, 0, 0, W2, tid, gm0, bn);

    for (int it = 0; it < G2_ITERS; it++) {
        CP_WAIT0();
        __syncthreads();
        int s = it & 1;
        if (it + 1 < G2_ITERS)
            g2_load_stage(smd, s ^ 1, (it + 1) * 64, W2, tid, gm0, bn);

        const uint32_t* A = smd + s * G2_STAGE_WORDS;
        const uint32_t* B = A + 4096;

        #pragma unroll
        for (int kk = 0; kk < 64; kk += 8) {
            uint32_t a[2][4];
            const int xo = 4 * g;
            #pragma unroll
            for (int mt = 0; mt < 2; mt++) {
                int r = wm + mt * 16 + g;
                a[mt][0] = A[(size_t)r * 64 + ((kk + tig) ^ xo)];
                a[mt][1] = A[(size_t)(r + 8) * 64 + ((kk + tig) ^ xo)];
                a[mt][2] = A[(size_t)r * 64 + ((kk + tig + 4) ^ xo)];
                a[mt][3] = A[(size_t)(r + 8) * 64 + ((kk + tig + 4) ^ xo)];
            }
            const int krow = kk + tig;
            const int ko   = (krow & 3) * 8;
            #pragma unroll
            for (int nt = 0; nt < 4; nt++) {
                int n  = wn + nt * 8 + g;
                int pc = n ^ ko;
                uint32_t b0 = B[krow * 128 + pc];
                uint32_t b1 = B[(krow + 4) * 128 + pc];
                #pragma unroll
                for (int mt = 0; mt < 2; mt++)
                    mma8(acc[mt][nt], a[mt][0], a[mt][1], a[mt][2], a[mt][3], b0, b1);
            }
        }
    }

    // epilogue: dense store into g_Y (guard rows >= cnt)
    #pragma unroll
    for (int mt = 0; mt < 2; mt++) {
        int lr0 = wm + mt * 16 + g;
        int lr1 = lr0 + 8;
        bool v0ok = (bm + lr0) < cnt;
        bool v1ok = (bm + lr1) < cnt;
        float* y0 = g_Y + (gm0 + lr0) * DIM;
        float* y1 = g_Y + (gm0 + lr1) * DIM;
        #pragma unroll
        for (int nt = 0; nt < 4; nt++) {
            int c = bn + wn + nt * 8 + 2 * tig;
            if (v0ok) *(float2*)&y0[c] = make_float2(acc[mt][nt][0], acc[mt][nt][1]);
            if (v1ok) *(float2*)&y1[c] = make_float2(acc[mt][nt][2], acc[mt][nt][3]);
        }
    }
}

// ---------------------------------------------------------------------------
// Combine: out[t] = sum over experts with g_slot[t][e] >= 0 of g_Y row.
// ---------------------------------------------------------------------------
__global__ void combine_kernel(float* __restrict__ out) {
    const int t  = blockIdx.x;
    const int tb = t >> 10;
    const int d  = threadIdx.x * 4;

    float4 acc = make_float4(0.f, 0.f, 0.f, 0.f);
    #pragma unroll
    for (int e = 0; e < EACT; e++) {
        int slot = g_slot[t * 4 + e];
        if (slot >= 0) {
            const float4 v = *(const float4*)&g_Y[((size_t)(e * NTB + tb) * TB + slot) * DIM + d];
            acc.x += v.x; acc.y += v.y; acc.z += v.z; acc.w += v.w;
        }
    }
    *(float4*)&out[(size_t)t * DIM + d] = acc;
}

// ---------------------------------------------------------------------------
extern "C" void kernel_launch(void* const* d_in, const int* in_sizes, int n_in,
                              void* d_out, int out_size) {
    const float* x   = (const float*)d_in[0];
    const float* gw  = (const float*)d_in[1];
    const float* w1  = (const float*)d_in[2];
    const float* w2  = (const float*)d_in[3];
    const float* w3  = (const float*)d_in[4];
    float* out = (float*)d_out;

    cudaFuncSetAttribute(gemm13_kernel,
                         cudaFuncAttributeMaxDynamicSharedMemorySize, 3 * G13_STAGE_WORDS * 4);
    cudaFuncSetAttribute(gemm2_kernel,
                         cudaFuncAttributeMaxDynamicSharedMemorySize, 2 * G2_STAGE_WORDS * 4);

    // Pre-convert operands to tf32 bits (experts 0..3 are the leading half).
    const size_t nW = (size_t)EACT * DIM * HID / 4;     // float4 count
    uint32_t* xt;  cudaGetSymbolAddress((void**)&xt,  g_Xt);
    uint32_t* w1t; cudaGetSymbolAddress((void**)&w1t, g_W1t);
    uint32_t* w3t; cudaGetSymbolAddress((void**)&w3t, g_W3t);
    uint32_t* w2t; cudaGetSymbolAddress((void**)&w2t, g_W2t);
    cvt4_kernel<<<2048, 256>>>((const float4*)x,  (uint4*)xt,  (size_t)T_TOK * DIM / 4);
    cvt4_kernel<<<2048, 256>>>((const float4*)w1, (uint4*)w1t, nW);
    cvt4_kernel<<<2048, 256>>>((const float4*)w3, (uint4*)w3t, nW);
    cvt4_kernel<<<2048, 256>>>((const float4*)w2, (uint4*)w2t, nW);

    gate_kernel<<<T_TOK / 4, 128>>>(x, gw);
    route_kernel<<<EACT * NTB, 256>>>();
    gemm13_kernel<<<dim3(HID / 64, TB / 128, EACT * NTB), 256, 3 * G13_STAGE_WORDS * 4>>>();
    gemm2_kernel<<<dim3(DIM / 128, TB / 64, EACT * NTB), 256, 2 * G2_STAGE_WORDS * 4>>>();
    combine_kernel<<<T_TOK, 256>>>(out);
}